// round 15
// baseline (speedup 1.0000x reference)
#include <cuda_runtime.h>
#include <cuda_bf16.h>
#include <cstdint>
#include <math.h>

#define BB     4096
#define TT     56
#define NSTEPS 28
#define HH     126
#define GG     378
#define ANN_   30
#define ENC_   20
#define DEC_   15

#define HS     128      // padded hidden stride
#define ROWS   14
#define NBLK   ((BB + ROWS - 1) / ROWS)   // 293

// row -> s_in slot (rows 0-6 -> 0-6, rows 7-13 -> 8-14; slots 7,15 zero)
#define SLOT(r) ((r) + ((r) >= 7 ? 1 : 0))

// ---------------- scratch (device globals; no allocations) ----------------
__device__ float g_h0[BB * HS];
__device__ float g_h1[BB * HS];
__device__ float g_enc_out[TT * BB * HS];
__device__ __nv_bfloat16 g_enc_bf[(size_t)TT * BB * HS];
__device__ __nv_bfloat16 g_Uobf[(size_t)TT * BB * HS];
__device__ float g_Wh[BB * HS];
__device__ float g_x[BB * HS];
__device__ float g_giE[(size_t)TT * BB * 384];
__device__ float g_giD[(size_t)NSTEPS * BB * 384];
__device__ float g_Wenc[128 * 384];
__device__ float g_Wdec[256 * 384];
__device__ float g_WgiE[ENC_ * 384];
__device__ float g_WgiD[DEC_ * 384];
__device__ float g_bgE[384];
__device__ float g_bgD[384];
__device__ float g_UWTp[HH * HS];
__device__ float g_WlTp[HH * HS];
__device__ float g_Ubp[HS];
__device__ float g_Wlbp[HS];
__device__ float g_Vp[HS];

// ---------------- fast transcendentals ----------------
__device__ __forceinline__ float ex2f(float x) { float y; asm("ex2.approx.f32 %0, %1;" : "=f"(y) : "f"(x)); return y; }
__device__ __forceinline__ float rcpf(float x) { float y; asm("rcp.approx.f32 %0, %1;" : "=f"(y) : "f"(x)); return y; }
__device__ __forceinline__ float tanha(float x) { float y; asm("tanh.approx.f32 %0, %1;" : "=f"(y) : "f"(x)); return y; }
#define LOG2E_ 1.4426950408889634f
__device__ __forceinline__ float sigf(float v)  { return rcpf(1.0f + ex2f(-v * LOG2E_)); }
__device__ __forceinline__ float tanhp(float v) { return 2.0f * rcpf(1.0f + ex2f(-2.0f * v * LOG2E_)) - 1.0f; }

// ---------------- packed f32x2 FMA ----------------
__device__ __forceinline__ unsigned long long dupf(float w) {
    unsigned long long r; asm("mov.b64 %0, {%1, %1};" : "=l"(r) : "f"(w)); return r;
}
__device__ __forceinline__ void fma2(unsigned long long& d, unsigned long long a, unsigned long long b) {
    asm("fma.rn.f32x2 %0, %1, %2, %0;" : "+l"(d) : "l"(a), "l"(b));
}
__device__ __forceinline__ float2 unpk(unsigned long long v) {
    float2 f; asm("mov.b64 {%0, %1}, %2;" : "=f"(f.x), "=f"(f.y) : "l"(v)); return f;
}

// ---------------- cp.async helpers ----------------
__device__ __forceinline__ void cpa16(unsigned dst, const void* src) {
    asm volatile("cp.async.cg.shared.global [%0], [%1], 16;" :: "r"(dst), "l"(src));
}
__device__ __forceinline__ void cpa_commit() { asm volatile("cp.async.commit_group;"); }
__device__ __forceinline__ void cpa_wait0()  { asm volatile("cp.async.wait_group 0;"); }

// ---------------- weight prep ----------------
__global__ void prep_weights(const float* __restrict__ eWih, const float* __restrict__ eWhh,
                             const float* __restrict__ dWih, const float* __restrict__ dWhh,
                             const float* __restrict__ U,    const float* __restrict__ Ub,
                             const float* __restrict__ Wl,   const float* __restrict__ Wlb,
                             const float* __restrict__ V,
                             const float* __restrict__ ebih, const float* __restrict__ ebhh,
                             const float* __restrict__ dbih, const float* __restrict__ dbhh) {
    int i = blockIdx.x * 256 + threadIdx.x;
    const int Nwe = 128 * 384, Nwd = 256 * 384, Nge = ENC_ * 384, Ngd = DEC_ * 384;
    const int Nuw = HH * HS;
    if (i < Nwe) {
        int k = i / 384, j = i % 384;
        g_Wenc[i] = (j < GG && k < HH) ? eWhh[j * HH + k] : 0.0f;
        return;
    }
    i -= Nwe;
    if (i < Nwd) {
        int k = i / 384, j = i % 384;
        float v = 0.0f;
        if (j < GG) {
            if (k < 126) v = dWih[j * 142 + 16 + k];
            else if (k == 126) v = dWih[j * 142 + 0];
            else if (k >= 128 && k < 254) v = dWhh[j * HH + (k - 128)];
        }
        g_Wdec[i] = v; return;
    }
    i -= Nwd;
    if (i < Nge) {
        int k = i / 384, j = i % 384;
        g_WgiE[i] = (j < GG) ? eWih[j * ENC_ + k] : 0.0f;
        return;
    }
    i -= Nge;
    if (i < Ngd) {
        int k = i / 384, j = i % 384;
        g_WgiD[i] = (j < GG) ? dWih[j * 142 + 1 + k] : 0.0f;
        return;
    }
    i -= Ngd;
    if (i < 384) {
        g_bgE[i] = (i < GG) ? (ebih[i] + ((i < 2 * HH) ? ebhh[i] : 0.0f)) : 0.0f;
        g_bgD[i] = (i < GG) ? (dbih[i] + ((i < 2 * HH) ? dbhh[i] : 0.0f)) : 0.0f;
        return;
    }
    i -= 384;
    if (i < Nuw) { int k = i / HS, j = i % HS; g_UWTp[i] = (j < HH) ? U[j * HH + k] : 0.0f; return; }
    i -= Nuw;
    if (i < Nuw) { int k = i / HS, j = i % HS; g_WlTp[i] = (j < HH) ? Wl[j * HH + k] : 0.0f; return; }
    i -= Nuw;
    if (i < HS) { g_Ubp[i] = (i < HH) ? Ub[i] : 0.0f; return; }
    i -= HS;
    if (i < HS) { g_Wlbp[i] = (i < HH) ? Wlb[i] : 0.0f; return; }
    i -= HS;
    if (i < HS) { g_Vp[i] = (i < HH) ? V[i] : 0.0f; }
}

// ---------------- s2h MLP ----------------
__global__ void s2h_kernel(const float* __restrict__ ann,
                           const float* __restrict__ W1, const float* __restrict__ b1,
                           const float* __restrict__ W2, const float* __restrict__ b2,
                           float* __restrict__ h) {
    __shared__ float a[ANN_];
    __shared__ float mid[96];
    int b = blockIdx.x;
    int tid = threadIdx.x;
    if (tid < ANN_) a[tid] = ann[b * ANN_ + tid];
    __syncthreads();
    if (tid < 96) {
        float acc = b1[tid];
        #pragma unroll
        for (int k = 0; k < ANN_; k++) acc += W1[tid * ANN_ + k] * a[k];
        mid[tid] = fmaxf(acc, 0.0f);
    }
    __syncthreads();
    if (tid < HH) {
        float acc = b2[tid];
        #pragma unroll 4
        for (int k = 0; k < 96; k++) acc += W2[tid * 96 + k] * mid[k];
        h[(size_t)b * HS + tid] = acc;
    }
}

// ---------------- gi GEMM (bias folded, f32x2) ----------------
template <int KD>
__global__ __launch_bounds__(384) void gi_kernel(const float* __restrict__ in,
                                                 const float* __restrict__ Wg,
                                                 const float* __restrict__ bg,
                                                 float* __restrict__ gi) {
    __shared__ float s_w[KD * 384];
    __shared__ float s_in[KD * 16];
    const int tid = threadIdx.x;
    const int b0 = blockIdx.x * 16;
    for (int i = tid; i < KD * 96; i += 384)
        reinterpret_cast<float4*>(s_w)[i] = reinterpret_cast<const float4*>(Wg)[i];
    for (int i = tid; i < KD * 16; i += 384) {
        int r = i / KD, k = i % KD;
        s_in[k * 16 + r] = in[(size_t)(b0 + r) * KD + k];
    }
    __syncthreads();
    unsigned long long accp[8];
    #pragma unroll
    for (int p = 0; p < 8; p++) accp[p] = dupf(0.0f);
    #pragma unroll 4
    for (int k = 0; k < KD; k++) {
        unsigned long long wd = dupf(s_w[k * 384 + tid]);
        const ulonglong2* sp2 = reinterpret_cast<const ulonglong2*>(s_in + k * 16);
        ulonglong2 q0 = sp2[0], q1 = sp2[1], q2 = sp2[2], q3 = sp2[3];
        fma2(accp[0], wd, q0.x); fma2(accp[1], wd, q0.y);
        fma2(accp[2], wd, q1.x); fma2(accp[3], wd, q1.y);
        fma2(accp[4], wd, q2.x); fma2(accp[5], wd, q2.y);
        fma2(accp[6], wd, q3.x); fma2(accp[7], wd, q3.y);
    }
    float bb = bg[tid];
    #pragma unroll
    for (int p = 0; p < 8; p++) {
        float2 f = unpk(accp[p]);
        gi[(size_t)(b0 + 2 * p) * 384 + tid]     = f.x + bb;
        gi[(size_t)(b0 + 2 * p + 1) * 384 + tid] = f.y + bb;
    }
}

// ---------------- encoder GRU step: 384 thr, 2 cols x 7 rows/thread --------
__global__ __launch_bounds__(384, 2) void gruE_kernel(
        const float* __restrict__ h_in,
        const float* __restrict__ W,      // [128][384]
        const float* __restrict__ gi,     // [row][384], biases folded
        const float* __restrict__ bhh,
        float* __restrict__ h_out,
        __nv_bfloat16* __restrict__ h_out_bf) {
    constexpr int KP = 128, NC = 8, CHF = 16 * 384;
    extern __shared__ float sm[];
    float* s_in   = sm;                        // 128*16
    float* pool   = sm + KP * 16;              // 2*CHF
    float* s_gi   = pool + 2 * CHF;            // ROWS*384
    float* s_preA = pool;
    float* s_preB = pool + GG * 15;

    const int tid = threadIdx.x;
    const int grp = tid / 192;     // row-half
    const int cid = tid % 192;     // column pair base
    const int b0 = blockIdx.x * ROWS;
    const int nrow = min(ROWS, BB - b0);
    unsigned pool_sa = (unsigned)__cvta_generic_to_shared(pool);
    unsigned sgi_sa  = (unsigned)__cvta_generic_to_shared(s_gi);

    {
        const float* gsrc = gi + (size_t)b0 * 384;
        for (int idx = tid; idx < nrow * 96; idx += 384)
            cpa16(sgi_sa + (unsigned)idx * 16u, gsrc + idx * 4);
        #pragma unroll
        for (int v = 0; v < 4; v++) {
            int u = tid + 384 * v;
            cpa16(pool_sa + (unsigned)u * 16u, W + (size_t)u * 4);
        }
        cpa_commit();
    }
    for (int i = tid; i < HH * ROWS; i += 384) {
        int r = i / HH, k = i % HH;
        s_in[k * 16 + SLOT(r)] = (r < nrow) ? h_in[(size_t)(b0 + r) * HS + k] : 0.0f;
    }
    // zero slots 7 and 15 for all k
    for (int i = tid; i < KP * 2; i += 384) {
        int k = i >> 1;
        s_in[k * 16 + ((i & 1) ? 15 : 7)] = 0.0f;
    }
    // zero pad k rows (126,127)
    for (int i = tid; i < 2 * 16; i += 384)
        s_in[(HH + i / 16) * 16 + (i % 16)] = 0.0f;
    cpa_wait0();
    __syncthreads();

    unsigned long long a0[4], a1[4];
    #pragma unroll
    for (int p = 0; p < 4; p++) { a0[p] = dupf(0.0f); a1[p] = dupf(0.0f); }

    for (int c = 0; c < NC; c++) {
        const int cur = c & 1;
        if (c + 1 < NC) {
            const float* base = W + (size_t)(c + 1) * CHF;
            unsigned dstb = pool_sa + (unsigned)(1 - cur) * CHF * 4u;
            #pragma unroll
            for (int v = 0; v < 4; v++) {
                int u = tid + 384 * v;
                cpa16(dstb + (unsigned)u * 16u, base + (size_t)u * 4);
            }
            cpa_commit();
        }
        const float* wp = pool + cur * CHF + cid;
        const float* ip = s_in + c * 16 * 16 + grp * 8;
        #pragma unroll
        for (int kk = 0; kk < 16; kk++) {
            unsigned long long w0 = dupf(wp[kk * 384]);
            unsigned long long w1 = dupf(wp[kk * 384 + 192]);
            const ulonglong2* sp2 = reinterpret_cast<const ulonglong2*>(ip + kk * 16);
            ulonglong2 q0 = sp2[0], q1 = sp2[1];
            fma2(a0[0], w0, q0.x); fma2(a0[1], w0, q0.y);
            fma2(a0[2], w0, q1.x); fma2(a0[3], w0, q1.y);
            fma2(a1[0], w1, q0.x); fma2(a1[1], w1, q0.y);
            fma2(a1[2], w1, q1.x); fma2(a1[3], w1, q1.y);
        }
        if (c + 1 < NC) cpa_wait0();
        __syncthreads();
    }

    {
        const int c0 = cid, c1 = cid + 192;
        float f0[8], f1[8];
        #pragma unroll
        for (int p = 0; p < 4; p++) {
            float2 u = unpk(a0[p]); f0[2*p] = u.x; f0[2*p+1] = u.y;
            float2 v = unpk(a1[p]); f1[2*p] = v.x; f1[2*p+1] = v.y;
        }
        #pragma unroll
        for (int q = 0; q < 7; q++) {
            int r = grp * 7 + q;
            float gv0 = s_gi[r * 384 + c0];
            s_preA[c0 * 15 + r] = f0[q] + gv0;
        }
        if (c1 < GG) {
            #pragma unroll
            for (int q = 0; q < 7; q++) {
                int r = grp * 7 + q;
                float gv1 = s_gi[r * 384 + c1];
                s_preA[c1 * 15 + r] = f1[q] + gv1;
                if (c1 >= 2 * HH) s_preB[(c1 - 2 * HH) * 15 + r] = gv1;
            }
        }
    }
    __syncthreads();

    for (int i = tid; i < ROWS * 128; i += 384) {
        int r = i >> 7;
        int j = i & 127;
        if (r >= nrow) continue;
        size_t oidx = (size_t)(b0 + r) * HS + j;
        if (j < HH) {
            float pr = s_preA[j * 15 + r];
            float pz = s_preA[(HH + j) * 15 + r];
            float nx = s_preB[j * 15 + r];
            float nh = s_preA[(2 * HH + j) * 15 + r] - nx + bhh[2 * HH + j];
            float rg = sigf(pr);
            float zg = sigf(pz);
            float nn = tanhp(nx + rg * nh);
            float hv = s_in[j * 16 + SLOT(r)];
            float hnew = (1.0f - zg) * nn + zg * hv;
            h_out[oidx] = hnew;
            h_out_bf[oidx] = __float2bfloat16(hnew);
        } else {
            h_out[oidx] = 0.0f;
            h_out_bf[oidx] = __float2bfloat16(0.0f);
        }
    }
}

// ---------------- decoder GRU step: 384 thr, 2 cols x 7 rows + fused Wh ----
__global__ __launch_bounds__(384, 2) void gruD_kernel(
        const float* __restrict__ h_in,
        const float* __restrict__ x,
        const float* __restrict__ W,      // [256][384]
        const float* __restrict__ gi,
        const float* __restrict__ bhh,
        float* __restrict__ h_out,
        const float* __restrict__ h2oW, const float* __restrict__ h2ob,
        float* __restrict__ out,
        const float* __restrict__ WlTp, const float* __restrict__ Wlbp,
        float* __restrict__ Wh) {
    constexpr int KP = 256, NC = 16, XDP = 128, CHF = 16 * 384;
    extern __shared__ float sm[];
    float* s_in   = sm;                        // 256*16
    float* pool   = sm + KP * 16;              // 2*CHF
    float* s_gi   = pool + 2 * CHF;            // ROWS*384
    float* s_preA = pool;
    float* s_preB = pool + GG * 15;
    float* s_out  = pool + GG * 15 + HH * 15;  // 14

    const int tid = threadIdx.x;
    const int lane = tid & 31;
    const int grp = tid / 192;
    const int cid = tid % 192;
    const int b0 = blockIdx.x * ROWS;
    const int nrow = min(ROWS, BB - b0);
    unsigned pool_sa = (unsigned)__cvta_generic_to_shared(pool);
    unsigned sgi_sa  = (unsigned)__cvta_generic_to_shared(s_gi);

    {
        const float* gsrc = gi + (size_t)b0 * 384;
        for (int idx = tid; idx < nrow * 96; idx += 384)
            cpa16(sgi_sa + (unsigned)idx * 16u, gsrc + idx * 4);
        #pragma unroll
        for (int v = 0; v < 4; v++) {
            int u = tid + 384 * v;
            cpa16(pool_sa + (unsigned)u * 16u, W + (size_t)u * 4);
        }
        cpa_commit();
    }
    for (int i = tid; i < 127 * ROWS; i += 384) {
        int r = i / 127, k = i % 127;
        s_in[k * 16 + SLOT(r)] = (r < nrow) ? x[(size_t)(b0 + r) * HS + k] : 0.0f;
    }
    for (int i = tid; i < HH * ROWS; i += 384) {
        int r = i / HH, k = i % HH;
        s_in[(XDP + k) * 16 + SLOT(r)] = (r < nrow) ? h_in[(size_t)(b0 + r) * HS + k] : 0.0f;
    }
    // zero slots 7 and 15 for all k
    for (int i = tid; i < KP * 2; i += 384) {
        int k = i >> 1;
        s_in[k * 16 + ((i & 1) ? 15 : 7)] = 0.0f;
    }
    // zero pad k rows: k=127, 254, 255
    for (int i = tid; i < 3 * 16; i += 384) {
        int kk = (i / 16 == 0) ? 127 : (XDP + HH + i / 16 - 1);
        s_in[kk * 16 + (i % 16)] = 0.0f;
    }
    cpa_wait0();
    __syncthreads();

    unsigned long long a0[4], a1[4], ax1[4];
    #pragma unroll
    for (int p = 0; p < 4; p++) { a0[p] = dupf(0.0f); a1[p] = dupf(0.0f); ax1[p] = dupf(0.0f); }

    for (int c = 0; c < NC; c++) {
        const int cur = c & 1;
        if (c + 1 < NC) {
            const float* base = W + (size_t)(c + 1) * CHF;
            unsigned dstb = pool_sa + (unsigned)(1 - cur) * CHF * 4u;
            #pragma unroll
            for (int v = 0; v < 4; v++) {
                int u = tid + 384 * v;
                cpa16(dstb + (unsigned)u * 16u, base + (size_t)u * 4);
            }
            cpa_commit();
        }
        const float* wp = pool + cur * CHF + cid;
        const float* ip = s_in + c * 16 * 16 + grp * 8;
        #pragma unroll
        for (int kk = 0; kk < 16; kk++) {
            unsigned long long w0 = dupf(wp[kk * 384]);
            unsigned long long w1 = dupf(wp[kk * 384 + 192]);
            const ulonglong2* sp2 = reinterpret_cast<const ulonglong2*>(ip + kk * 16);
            ulonglong2 q0 = sp2[0], q1 = sp2[1];
            fma2(a0[0], w0, q0.x); fma2(a0[1], w0, q0.y);
            fma2(a0[2], w0, q1.x); fma2(a0[3], w0, q1.y);
            fma2(a1[0], w1, q0.x); fma2(a1[1], w1, q0.y);
            fma2(a1[2], w1, q1.x); fma2(a1[3], w1, q1.y);
        }
        if (c == 7) {
            #pragma unroll
            for (int p = 0; p < 4; p++) ax1[p] = a1[p];   // only col1 can be n-gate
        }
        if (c + 1 < NC) cpa_wait0();
        __syncthreads();
    }

    {
        const int c0 = cid, c1 = cid + 192;
        float f0[8], f1[8], fx1[8];
        #pragma unroll
        for (int p = 0; p < 4; p++) {
            float2 u = unpk(a0[p]); f0[2*p] = u.x; f0[2*p+1] = u.y;
            float2 v = unpk(a1[p]); f1[2*p] = v.x; f1[2*p+1] = v.y;
            float2 w = unpk(ax1[p]); fx1[2*p] = w.x; fx1[2*p+1] = w.y;
        }
        #pragma unroll
        for (int q = 0; q < 7; q++) {
            int r = grp * 7 + q;
            float gv0 = s_gi[r * 384 + c0];
            s_preA[c0 * 15 + r] = f0[q] + gv0;
        }
        if (c1 < GG) {
            #pragma unroll
            for (int q = 0; q < 7; q++) {
                int r = grp * 7 + q;
                float gv1 = s_gi[r * 384 + c1];
                s_preA[c1 * 15 + r] = f1[q] + gv1;
                if (c1 >= 2 * HH) s_preB[(c1 - 2 * HH) * 15 + r] = fx1[q] + gv1;
            }
        }
    }
    if (tid < ROWS) s_out[tid] = 0.0f;
    __syncthreads();

    // gates + h2o; hnew written back into s_in h-region for Wh GEMM
    for (int i = tid; i < ROWS * 128; i += 384) {
        int r = i >> 7;
        int j = i & 127;
        float val = 0.0f;
        if (r < nrow && j < HH) {
            float pr = s_preA[j * 15 + r];
            float pz = s_preA[(HH + j) * 15 + r];
            float nx = s_preB[j * 15 + r];
            float nh = s_preA[(2 * HH + j) * 15 + r] - nx + bhh[2 * HH + j];
            float rg = sigf(pr);
            float zg = sigf(pz);
            float nn = tanhp(nx + rg * nh);
            float hv = s_in[(XDP + j) * 16 + SLOT(r)];
            float hnew = (1.0f - zg) * nn + zg * hv;
            h_out[(size_t)(b0 + r) * HS + j] = hnew;
            s_in[(XDP + j) * 16 + SLOT(r)] = hnew;
            val = hnew * h2oW[j];
        }
        #pragma unroll
        for (int off = 16; off; off >>= 1) val += __shfl_down_sync(0xffffffffu, val, off);
        if (lane == 0 && r < nrow) atomicAdd(&s_out[r], val);
    }
    __syncthreads();
    if (tid < nrow) out[b0 + tid] = s_out[tid] + h2ob[0];

    // fused Wh for the NEXT step: 256 threads, col j, row-half g
    if (tid < 256) {
        const int j = tid & 127;
        const int g = tid >> 7;
        unsigned long long wa[4];
        #pragma unroll
        for (int p = 0; p < 4; p++) wa[p] = dupf(0.0f);
        #pragma unroll 2
        for (int k = 0; k < HH; k++) {
            unsigned long long wd = dupf(WlTp[k * HS + j]);
            const ulonglong2* sp2 = reinterpret_cast<const ulonglong2*>(s_in + (XDP + k) * 16 + g * 8);
            ulonglong2 q0 = sp2[0], q1 = sp2[1];
            fma2(wa[0], wd, q0.x); fma2(wa[1], wd, q0.y);
            fma2(wa[2], wd, q1.x); fma2(wa[3], wd, q1.y);
        }
        float bj = Wlbp[j];
        float f[8];
        #pragma unroll
        for (int p = 0; p < 4; p++) {
            float2 u = unpk(wa[p]); f[2*p] = u.x; f[2*p+1] = u.y;
        }
        #pragma unroll
        for (int q = 0; q < 7; q++) {
            int r = g * 7 + q;
            if (r < nrow) Wh[(size_t)(b0 + r) * HS + j] = f[q] + bj;
        }
    }
}

// ---------------- dense [rows x 126] @ [126 x 128] + bias (f32x2) ----------
template <bool BF16OUT>
__global__ __launch_bounds__(256, 2) void lin_kernel(const float* __restrict__ in,
                                                     const float* __restrict__ Wp,
                                                     const float* __restrict__ biasp,
                                                     float* __restrict__ outf,
                                                     __nv_bfloat16* __restrict__ outb) {
    constexpr int P2 = 36;
    extern __shared__ float sm[];
    float* s_w  = sm;
    float* s_in = sm + HH * HS;
    const int tid = threadIdx.x;
    const int b0 = blockIdx.x * 32;

    {
        const float4* src = reinterpret_cast<const float4*>(Wp);
        float4* dst = reinterpret_cast<float4*>(s_w);
        for (int v = tid; v < HH * HS / 4; v += 256) dst[v] = src[v];
    }
    for (int idx = tid; idx < HH * 32; idx += 256) {
        int r = idx / HH, k = idx % HH;
        s_in[k * P2 + r] = in[(size_t)(b0 + r) * HS + k];
    }
    __syncthreads();

    const int j = tid & 127;
    const int half = tid >> 7;
    unsigned long long accp[8];
    #pragma unroll
    for (int p = 0; p < 8; p++) accp[p] = dupf(0.0f);
    #pragma unroll 2
    for (int k = 0; k < HH; k++) {
        unsigned long long wd = dupf(s_w[k * HS + j]);
        const ulonglong2* sp2 = reinterpret_cast<const ulonglong2*>(s_in + k * P2 + half * 16);
        ulonglong2 q0 = sp2[0], q1 = sp2[1], q2 = sp2[2], q3 = sp2[3];
        fma2(accp[0], wd, q0.x); fma2(accp[1], wd, q0.y);
        fma2(accp[2], wd, q1.x); fma2(accp[3], wd, q1.y);
        fma2(accp[4], wd, q2.x); fma2(accp[5], wd, q2.y);
        fma2(accp[6], wd, q3.x); fma2(accp[7], wd, q3.y);
    }
    float bj = biasp[j];
    #pragma unroll
    for (int p = 0; p < 8; p++) {
        float2 f = unpk(accp[p]);
        size_t i0 = (size_t)(b0 + half * 16 + 2 * p) * HS + j;
        size_t i1 = (size_t)(b0 + half * 16 + 2 * p + 1) * HS + j;
        if (BF16OUT) {
            outb[i0] = __float2bfloat16(f.x + bj);
            outb[i1] = __float2bfloat16(f.y + bj);
        } else {
            outf[i0] = f.x + bj;
            outf[i1] = f.y + bj;
        }
    }
}

// ---------------- fused attention: scores + softmax + context + x ----------
__global__ __launch_bounds__(128) void attn_kernel(
        const __nv_bfloat16* __restrict__ Uobf, const float* __restrict__ Wh,
        const float* __restrict__ Vp, const float* __restrict__ Vb,
        const __nv_bfloat16* __restrict__ encbf,
        const float* __restrict__ enc_data, const float* __restrict__ outbuf,
        float* __restrict__ x, int step) {
    __shared__ float sal[TT * 4];
    const int tid = threadIdx.x;
    const int warp = tid >> 5, lane = tid & 31;
    const int row = blockIdx.x * 4 + warp;

    const float4 wh = *(reinterpret_cast<const float4*>(Wh + (size_t)row * HS) + lane);
    const float4 vv = *(reinterpret_cast<const float4*>(Vp) + lane);
    const float vb = Vb[0];

    #pragma unroll 4
    for (int t = 0; t < TT; t++) {
        uint2 p = *(reinterpret_cast<const uint2*>(Uobf + ((size_t)t * BB + row) * HS) + lane);
        float2 u0 = __bfloat1622float2(*reinterpret_cast<const __nv_bfloat162*>(&p.x));
        float2 u1 = __bfloat1622float2(*reinterpret_cast<const __nv_bfloat162*>(&p.y));
        float a = tanha(u0.x + wh.x) * vv.x + tanha(u0.y + wh.y) * vv.y
                + tanha(u1.x + wh.z) * vv.z + tanha(u1.y + wh.w) * vv.w;
        #pragma unroll
        for (int off = 16; off; off >>= 1) a += __shfl_down_sync(0xffffffffu, a, off);
        if (lane == 0) sal[t * 4 + warp] = a + vb;
    }
    __syncthreads();

    if (tid < 4) {
        float mx = -1e30f;
        for (int t = 0; t < TT; t++) mx = fmaxf(mx, sal[t * 4 + tid]);
        float sum = 0.0f;
        for (int t = 0; t < TT; t++) {
            float e = ex2f((sal[t * 4 + tid] - mx) * LOG2E_);
            sal[t * 4 + tid] = e;
            sum += e;
        }
        float inv = rcpf(sum);
        for (int t = 0; t < TT; t++) sal[t * 4 + tid] *= inv;
    }
    __syncthreads();

    float4 acc = {0.f, 0.f, 0.f, 0.f};
    #pragma unroll 4
    for (int t = 0; t < TT; t++) {
        float al = sal[t * 4 + warp];
        uint2 p = *(reinterpret_cast<const uint2*>(encbf + ((size_t)t * BB + row) * HS) + lane);
        float2 e0 = __bfloat1622float2(*reinterpret_cast<const __nv_bfloat162*>(&p.x));
        float2 e1 = __bfloat1622float2(*reinterpret_cast<const __nv_bfloat162*>(&p.y));
        acc.x += al * e0.x; acc.y += al * e0.y; acc.z += al * e1.x; acc.w += al * e1.y;
    }
    float* xr = x + (size_t)row * HS;
    if (lane < 31) {
        *(reinterpret_cast<float4*>(xr) + lane) = acc;
    } else {
        xr[124] = acc.x;
        xr[125] = acc.y;
    }
    if (lane == 0) {
        float prev = (step == 0) ? enc_data[((size_t)(TT - 1) * BB + row) * ENC_]
                                 : outbuf[(size_t)(step - 1) * BB + row];
        xr[126] = prev;
    }
}

// ---------------- host side ----------------
extern "C" void kernel_launch(void* const* d_in, const int* in_sizes, int n_in,
                              void* d_out, int out_size) {
    const float* ann      = (const float*)d_in[0];
    const float* enc_data = (const float*)d_in[1];
    const float* dec_data = (const float*)d_in[2];
    const float* s2h_W1   = (const float*)d_in[3];
    const float* s2h_b1   = (const float*)d_in[4];
    const float* s2h_W2   = (const float*)d_in[5];
    const float* s2h_b2   = (const float*)d_in[6];
    const float* enc_Wih  = (const float*)d_in[7];
    const float* enc_Whh  = (const float*)d_in[8];
    const float* enc_bih  = (const float*)d_in[9];
    const float* enc_bhh  = (const float*)d_in[10];
    const float* dec_Wih  = (const float*)d_in[11];
    const float* dec_Whh  = (const float*)d_in[12];
    const float* dec_bih  = (const float*)d_in[13];
    const float* dec_bhh  = (const float*)d_in[14];
    const float* U_W      = (const float*)d_in[15];
    const float* U_b      = (const float*)d_in[16];
    const float* Wl_W     = (const float*)d_in[17];
    const float* Wl_b     = (const float*)d_in[18];
    const float* V_W      = (const float*)d_in[19];
    const float* V_b      = (const float*)d_in[20];
    const float* h2o_W    = (const float*)d_in[21];
    const float* h2o_b    = (const float*)d_in[22];
    float* outp = (float*)d_out;

    float *h0, *h1, *enc_out, *Wh, *x, *giE, *giD;
    float *Wenc, *Wdec, *WgiE, *WgiD, *bgE, *bgD, *UWTp, *WlTp, *Ubp, *Wlbp, *Vp;
    __nv_bfloat16 *Uobf, *encbf;
    cudaGetSymbolAddress((void**)&h0, g_h0);
    cudaGetSymbolAddress((void**)&h1, g_h1);
    cudaGetSymbolAddress((void**)&enc_out, g_enc_out);
    cudaGetSymbolAddress((void**)&encbf, g_enc_bf);
    cudaGetSymbolAddress((void**)&Uobf, g_Uobf);
    cudaGetSymbolAddress((void**)&Wh, g_Wh);
    cudaGetSymbolAddress((void**)&x, g_x);
    cudaGetSymbolAddress((void**)&giE, g_giE);
    cudaGetSymbolAddress((void**)&giD, g_giD);
    cudaGetSymbolAddress((void**)&Wenc, g_Wenc);
    cudaGetSymbolAddress((void**)&Wdec, g_Wdec);
    cudaGetSymbolAddress((void**)&WgiE, g_WgiE);
    cudaGetSymbolAddress((void**)&WgiD, g_WgiD);
    cudaGetSymbolAddress((void**)&bgE, g_bgE);
    cudaGetSymbolAddress((void**)&bgD, g_bgD);
    cudaGetSymbolAddress((void**)&UWTp, g_UWTp);
    cudaGetSymbolAddress((void**)&WlTp, g_WlTp);
    cudaGetSymbolAddress((void**)&Ubp, g_Ubp);
    cudaGetSymbolAddress((void**)&Wlbp, g_Wlbp);
    cudaGetSymbolAddress((void**)&Vp, g_Vp);

    const size_t sm_enc = (size_t)(128 * 16 + 2 * 16 * 384 + ROWS * 384) * 4;  // 78848
    const size_t sm_dec = (size_t)(256 * 16 + 2 * 16 * 384 + ROWS * 384) * 4;  // 87040
    const size_t sm_uo  = (size_t)(HH * HS + HH * 36) * 4;
    cudaFuncSetAttribute((const void*)gruE_kernel,
                         cudaFuncAttributeMaxDynamicSharedMemorySize, (int)sm_enc);
    cudaFuncSetAttribute((const void*)gruD_kernel,
                         cudaFuncAttributeMaxDynamicSharedMemorySize, (int)sm_dec);
    cudaFuncSetAttribute((const void*)lin_kernel<false>,
                         cudaFuncAttributeMaxDynamicSharedMemorySize, (int)sm_uo);
    cudaFuncSetAttribute((const void*)lin_kernel<true>,
                         cudaFuncAttributeMaxDynamicSharedMemorySize, (int)sm_uo);

    const int total_w = 128 * 384 + 256 * 384 + ENC_ * 384 + DEC_ * 384 + 384
                      + 2 * HH * HS + 3 * HS;
    prep_weights<<<(total_w + 255) / 256, 256>>>(enc_Wih, enc_Whh, dec_Wih, dec_Whh,
                                                 U_W, U_b, Wl_W, Wl_b, V_W,
                                                 enc_bih, enc_bhh, dec_bih, dec_bhh);

    s2h_kernel<<<BB, 128>>>(ann, s2h_W1, s2h_b1, s2h_W2, s2h_b2, h0);

    gi_kernel<ENC_><<<TT * BB / 16, 384>>>(enc_data, WgiE, bgE, giE);

    for (int t = 0; t < TT; t++) {
        const float* hin = (t == 0) ? h0 : enc_out + (size_t)(t - 1) * BB * HS;
        gruE_kernel<<<NBLK, 384, sm_enc>>>(
            hin, Wenc, giE + (size_t)t * BB * 384, enc_bhh,
            enc_out + (size_t)t * BB * HS, encbf + (size_t)t * BB * HS);
    }

    gi_kernel<DEC_><<<NSTEPS * BB / 16, 384>>>(dec_data, WgiD, bgD, giD);

    // Uo in bf16 (written once, streamed 28x)
    lin_kernel<true><<<TT * BB / 32, 256, sm_uo>>>(enc_out, UWTp, Ubp, nullptr, Uobf);

    const float* enc_last = enc_out + (size_t)(TT - 1) * BB * HS;
    lin_kernel<false><<<BB / 32, 256, sm_uo>>>(enc_last, WlTp, Wlbp, Wh, nullptr);

    for (int s = 0; s < NSTEPS; s++) {
        const float* hcur = (s == 0) ? enc_last : ((s & 1) ? h0 : h1);
        float* hnext      = (s & 1) ? h1 : h0;
        attn_kernel<<<BB / 4, 128>>>(Uobf, Wh, Vp, V_b, encbf, enc_data, outp, x, s);
        gruD_kernel<<<NBLK, 384, sm_dec>>>(
            hcur, x, Wdec, giD + (size_t)s * BB * 384, dec_bhh, hnext,
            h2o_W, h2o_b, outp + (size_t)s * BB, WlTp, Wlbp, Wh);
    }
}

// round 16
// speedup vs baseline: 1.0870x; 1.0870x over previous
#include <cuda_runtime.h>
#include <cuda_bf16.h>
#include <cstdint>
#include <math.h>

#define BB     4096
#define TT     56
#define NSTEPS 28
#define HH     126
#define GG     378
#define ANN_   30
#define ENC_   20
#define DEC_   15

#define HS     128
#define ROWS   14
#define NBLK   ((BB + ROWS - 1) / ROWS)   // 293

#define SLOT(r) ((r) + ((r) >= 7 ? 1 : 0))

// ---------------- scratch ----------------
__device__ float g_h0[BB * HS];
__device__ float g_h1[BB * HS];
__device__ float g_enc_out[TT * BB * HS];
__device__ __nv_bfloat16 g_enc_bf[(size_t)TT * BB * HS];
__device__ __nv_bfloat16 g_Uobf[(size_t)TT * BB * HS];
__device__ float g_Wh[BB * HS];
__device__ float g_x[BB * HS];
__device__ float g_giE[(size_t)TT * BB * 384];
__device__ float g_giD[(size_t)NSTEPS * BB * 384];
__device__ float g_Wenc[128 * 384];
__device__ float g_Wdec[256 * 384];
__device__ float g_WgiE[ENC_ * 384];
__device__ float g_WgiD[DEC_ * 384];
__device__ float g_bgE[384];
__device__ float g_bgD[384];
__device__ float g_UWTp[HH * HS];
__device__ float g_WlTp[HH * HS];
__device__ float g_Ubp[HS];
__device__ float g_Wlbp[HS];
__device__ float g_Vp[HS];

// ---------------- fast transcendentals ----------------
__device__ __forceinline__ float ex2f(float x) { float y; asm("ex2.approx.f32 %0, %1;" : "=f"(y) : "f"(x)); return y; }
__device__ __forceinline__ float rcpf(float x) { float y; asm("rcp.approx.f32 %0, %1;" : "=f"(y) : "f"(x)); return y; }
__device__ __forceinline__ float tanha(float x) { float y; asm("tanh.approx.f32 %0, %1;" : "=f"(y) : "f"(x)); return y; }
#define LOG2E_ 1.4426950408889634f
__device__ __forceinline__ float sigf(float v)  { return rcpf(1.0f + ex2f(-v * LOG2E_)); }
__device__ __forceinline__ float tanhp(float v) { return 2.0f * rcpf(1.0f + ex2f(-2.0f * v * LOG2E_)) - 1.0f; }

// ---------------- packed f32x2 FMA ----------------
__device__ __forceinline__ unsigned long long dupf(float w) {
    unsigned long long r; asm("mov.b64 %0, {%1, %1};" : "=l"(r) : "f"(w)); return r;
}
__device__ __forceinline__ void fma2(unsigned long long& d, unsigned long long a, unsigned long long b) {
    asm("fma.rn.f32x2 %0, %1, %2, %0;" : "+l"(d) : "l"(a), "l"(b));
}
__device__ __forceinline__ float2 unpk(unsigned long long v) {
    float2 f; asm("mov.b64 {%0, %1}, %2;" : "=f"(f.x), "=f"(f.y) : "l"(v)); return f;
}

// ---------------- cp.async ----------------
__device__ __forceinline__ void cpa16(unsigned dst, const void* src) {
    asm volatile("cp.async.cg.shared.global [%0], [%1], 16;" :: "r"(dst), "l"(src));
}
__device__ __forceinline__ void cpa_commit() { asm volatile("cp.async.commit_group;"); }
__device__ __forceinline__ void cpa_wait0()  { asm volatile("cp.async.wait_group 0;"); }

// ---------------- weight prep ----------------
__global__ void prep_weights(const float* __restrict__ eWih, const float* __restrict__ eWhh,
                             const float* __restrict__ dWih, const float* __restrict__ dWhh,
                             const float* __restrict__ U,    const float* __restrict__ Ub,
                             const float* __restrict__ Wl,   const float* __restrict__ Wlb,
                             const float* __restrict__ V,
                             const float* __restrict__ ebih, const float* __restrict__ ebhh,
                             const float* __restrict__ dbih, const float* __restrict__ dbhh) {
    int i = blockIdx.x * 256 + threadIdx.x;
    const int Nwe = 128 * 384, Nwd = 256 * 384, Nge = ENC_ * 384, Ngd = DEC_ * 384;
    const int Nuw = HH * HS;
    if (i < Nwe) {
        int k = i / 384, j = i % 384;
        g_Wenc[i] = (j < GG && k < HH) ? eWhh[j * HH + k] : 0.0f;
        return;
    }
    i -= Nwe;
    if (i < Nwd) {
        int k = i / 384, j = i % 384;
        float v = 0.0f;
        if (j < GG) {
            if (k < 126) v = dWih[j * 142 + 16 + k];
            else if (k == 126) v = dWih[j * 142 + 0];
            else if (k >= 128 && k < 254) v = dWhh[j * HH + (k - 128)];
        }
        g_Wdec[i] = v; return;
    }
    i -= Nwd;
    if (i < Nge) {
        int k = i / 384, j = i % 384;
        g_WgiE[i] = (j < GG) ? eWih[j * ENC_ + k] : 0.0f;
        return;
    }
    i -= Nge;
    if (i < Ngd) {
        int k = i / 384, j = i % 384;
        g_WgiD[i] = (j < GG) ? dWih[j * 142 + 1 + k] : 0.0f;
        return;
    }
    i -= Ngd;
    if (i < 384) {
        g_bgE[i] = (i < GG) ? (ebih[i] + ((i < 2 * HH) ? ebhh[i] : 0.0f)) : 0.0f;
        g_bgD[i] = (i < GG) ? (dbih[i] + ((i < 2 * HH) ? dbhh[i] : 0.0f)) : 0.0f;
        return;
    }
    i -= 384;
    if (i < Nuw) { int k = i / HS, j = i % HS; g_UWTp[i] = (j < HH) ? U[j * HH + k] : 0.0f; return; }
    i -= Nuw;
    if (i < Nuw) { int k = i / HS, j = i % HS; g_WlTp[i] = (j < HH) ? Wl[j * HH + k] : 0.0f; return; }
    i -= Nuw;
    if (i < HS) { g_Ubp[i] = (i < HH) ? Ub[i] : 0.0f; return; }
    i -= HS;
    if (i < HS) { g_Wlbp[i] = (i < HH) ? Wlb[i] : 0.0f; return; }
    i -= HS;
    if (i < HS) { g_Vp[i] = (i < HH) ? V[i] : 0.0f; }
}

// ---------------- s2h MLP ----------------
__global__ void s2h_kernel(const float* __restrict__ ann,
                           const float* __restrict__ W1, const float* __restrict__ b1,
                           const float* __restrict__ W2, const float* __restrict__ b2,
                           float* __restrict__ h) {
    __shared__ float a[ANN_];
    __shared__ float mid[96];
    int b = blockIdx.x;
    int tid = threadIdx.x;
    if (tid < ANN_) a[tid] = ann[b * ANN_ + tid];
    __syncthreads();
    if (tid < 96) {
        float acc = b1[tid];
        #pragma unroll
        for (int k = 0; k < ANN_; k++) acc += W1[tid * ANN_ + k] * a[k];
        mid[tid] = fmaxf(acc, 0.0f);
    }
    __syncthreads();
    if (tid < HH) {
        float acc = b2[tid];
        #pragma unroll 4
        for (int k = 0; k < 96; k++) acc += W2[tid * 96 + k] * mid[k];
        h[(size_t)b * HS + tid] = acc;
    }
}

// ---------------- gi GEMM (bias folded, f32x2) ----------------
template <int KD>
__global__ __launch_bounds__(384) void gi_kernel(const float* __restrict__ in,
                                                 const float* __restrict__ Wg,
                                                 const float* __restrict__ bg,
                                                 float* __restrict__ gi) {
    __shared__ float s_w[KD * 384];
    __shared__ float s_in[KD * 16];
    const int tid = threadIdx.x;
    const int b0 = blockIdx.x * 16;
    for (int i = tid; i < KD * 96; i += 384)
        reinterpret_cast<float4*>(s_w)[i] = reinterpret_cast<const float4*>(Wg)[i];
    for (int i = tid; i < KD * 16; i += 384) {
        int r = i / KD, k = i % KD;
        s_in[k * 16 + r] = in[(size_t)(b0 + r) * KD + k];
    }
    __syncthreads();
    unsigned long long accp[8];
    #pragma unroll
    for (int p = 0; p < 8; p++) accp[p] = dupf(0.0f);
    #pragma unroll 4
    for (int k = 0; k < KD; k++) {
        unsigned long long wd = dupf(s_w[k * 384 + tid]);
        const ulonglong2* sp2 = reinterpret_cast<const ulonglong2*>(s_in + k * 16);
        ulonglong2 q0 = sp2[0], q1 = sp2[1], q2 = sp2[2], q3 = sp2[3];
        fma2(accp[0], wd, q0.x); fma2(accp[1], wd, q0.y);
        fma2(accp[2], wd, q1.x); fma2(accp[3], wd, q1.y);
        fma2(accp[4], wd, q2.x); fma2(accp[5], wd, q2.y);
        fma2(accp[6], wd, q3.x); fma2(accp[7], wd, q3.y);
    }
    float bb = bg[tid];
    #pragma unroll
    for (int p = 0; p < 8; p++) {
        float2 f = unpk(accp[p]);
        gi[(size_t)(b0 + 2 * p) * 384 + tid]     = f.x + bb;
        gi[(size_t)(b0 + 2 * p + 1) * 384 + tid] = f.y + bb;
    }
}

// ---------------- PERSISTENT encoder: all 56 steps in one launch -----------
// 293 blocks (all resident at 2/SM), each owns 14 rows; h lives in smem.
__global__ __launch_bounds__(384, 2) void gruE_all_kernel(
        const float* __restrict__ h0,
        const float* __restrict__ W,      // [128][384]
        const float* __restrict__ giE,    // [t][row][384]
        const float* __restrict__ bhh,
        float* __restrict__ enc_out,
        __nv_bfloat16* __restrict__ enc_bf) {
    constexpr int KP = 128, NC = 8, CHF = 16 * 384;
    extern __shared__ float sm[];
    float* s_in   = sm;                        // 128*16
    float* pool   = sm + KP * 16;              // 2*CHF (aliased w/ preacts)
    float* s_gi   = pool + 2 * CHF;            // ROWS*384
    float* s_preA = pool;
    float* s_preB = pool + GG * 15;

    const int tid = threadIdx.x;
    const int grp = tid / 192;
    const int cid = tid % 192;
    const int b0 = blockIdx.x * ROWS;
    const int nrow = min(ROWS, BB - b0);
    unsigned pool_sa = (unsigned)__cvta_generic_to_shared(pool);
    unsigned sgi_sa  = (unsigned)__cvta_generic_to_shared(s_gi);

    // one-time: load h0 into s_in, zero pads
    for (int i = tid; i < HH * ROWS; i += 384) {
        int r = i / HH, k = i % HH;
        s_in[k * 16 + SLOT(r)] = (r < nrow) ? h0[(size_t)(b0 + r) * HS + k] : 0.0f;
    }
    for (int i = tid; i < KP * 2; i += 384) {
        int k = i >> 1;
        s_in[k * 16 + ((i & 1) ? 15 : 7)] = 0.0f;
    }
    for (int i = tid; i < 2 * 16; i += 384)
        s_in[(HH + i / 16) * 16 + (i % 16)] = 0.0f;
    __syncthreads();

    for (int t = 0; t < TT; t++) {
        // prefetch this step's gi + weight chunk 0
        {
            const float* gsrc = giE + ((size_t)t * BB + b0) * 384;
            for (int idx = tid; idx < nrow * 96; idx += 384)
                cpa16(sgi_sa + (unsigned)idx * 16u, gsrc + idx * 4);
            #pragma unroll
            for (int v = 0; v < 4; v++) {
                int u = tid + 384 * v;
                cpa16(pool_sa + (unsigned)u * 16u, W + (size_t)u * 4);
            }
            cpa_commit();
        }
        cpa_wait0();
        __syncthreads();

        unsigned long long a0[4], a1[4];
        #pragma unroll
        for (int p = 0; p < 4; p++) { a0[p] = dupf(0.0f); a1[p] = dupf(0.0f); }

        for (int c = 0; c < NC; c++) {
            const int cur = c & 1;
            if (c + 1 < NC) {
                const float* base = W + (size_t)(c + 1) * CHF;
                unsigned dstb = pool_sa + (unsigned)(1 - cur) * CHF * 4u;
                #pragma unroll
                for (int v = 0; v < 4; v++) {
                    int u = tid + 384 * v;
                    cpa16(dstb + (unsigned)u * 16u, base + (size_t)u * 4);
                }
                cpa_commit();
            }
            const float* wp = pool + cur * CHF + cid;
            const float* ip = s_in + c * 16 * 16 + grp * 8;
            #pragma unroll
            for (int kk = 0; kk < 16; kk++) {
                unsigned long long w0 = dupf(wp[kk * 384]);
                unsigned long long w1 = dupf(wp[kk * 384 + 192]);
                const ulonglong2* sp2 = reinterpret_cast<const ulonglong2*>(ip + kk * 16);
                ulonglong2 q0 = sp2[0], q1 = sp2[1];
                fma2(a0[0], w0, q0.x); fma2(a0[1], w0, q0.y);
                fma2(a0[2], w0, q1.x); fma2(a0[3], w0, q1.y);
                fma2(a1[0], w1, q0.x); fma2(a1[1], w1, q0.y);
                fma2(a1[2], w1, q1.x); fma2(a1[3], w1, q1.y);
            }
            if (c + 1 < NC) cpa_wait0();
            __syncthreads();
        }

        // preacts (pool now dead as weight buffer)
        {
            const int c0 = cid, c1 = cid + 192;
            float f0[8], f1[8];
            #pragma unroll
            for (int p = 0; p < 4; p++) {
                float2 u = unpk(a0[p]); f0[2*p] = u.x; f0[2*p+1] = u.y;
                float2 v = unpk(a1[p]); f1[2*p] = v.x; f1[2*p+1] = v.y;
            }
            #pragma unroll
            for (int q = 0; q < 7; q++) {
                int r = grp * 7 + q;
                float gv0 = s_gi[r * 384 + c0];
                s_preA[c0 * 15 + r] = f0[q] + gv0;
            }
            if (c1 < GG) {
                #pragma unroll
                for (int q = 0; q < 7; q++) {
                    int r = grp * 7 + q;
                    float gv1 = s_gi[r * 384 + c1];
                    s_preA[c1 * 15 + r] = f1[q] + gv1;
                    if (c1 >= 2 * HH) s_preB[(c1 - 2 * HH) * 15 + r] = gv1;
                }
            }
        }
        __syncthreads();

        // gates: hnew -> s_in (stays resident), enc_out, enc_bf
        float* eo = enc_out + (size_t)t * BB * HS;
        __nv_bfloat16* eb = enc_bf + (size_t)t * BB * HS;
        for (int i = tid; i < ROWS * 128; i += 384) {
            int r = i >> 7;
            int j = i & 127;
            if (r >= nrow) continue;
            size_t oidx = (size_t)(b0 + r) * HS + j;
            if (j < HH) {
                float pr = s_preA[j * 15 + r];
                float pz = s_preA[(HH + j) * 15 + r];
                float nx = s_preB[j * 15 + r];
                float nh = s_preA[(2 * HH + j) * 15 + r] - nx + bhh[2 * HH + j];
                float rg = sigf(pr);
                float zg = sigf(pz);
                float nn = tanhp(nx + rg * nh);
                float hv = s_in[j * 16 + SLOT(r)];
                float hnew = (1.0f - zg) * nn + zg * hv;
                s_in[j * 16 + SLOT(r)] = hnew;
                eo[oidx - (size_t)b0 * HS + (size_t)b0 * HS] = hnew;  // = eo[oidx]
                eo[oidx] = hnew;
                eb[oidx] = __float2bfloat16(hnew);
            } else {
                eo[oidx] = 0.0f;
                eb[oidx] = __float2bfloat16(0.0f);
            }
        }
        __syncthreads();   // protect pool/s_gi from next iter's prefetch
    }
}

// ---------------- decoder GRU step: 384 thr, 2 cols x 7 rows + fused Wh ----
__global__ __launch_bounds__(384, 2) void gruD_kernel(
        const float* __restrict__ h_in,
        const float* __restrict__ x,
        const float* __restrict__ W,      // [256][384]
        const float* __restrict__ gi,
        const float* __restrict__ bhh,
        float* __restrict__ h_out,
        const float* __restrict__ h2oW, const float* __restrict__ h2ob,
        float* __restrict__ out,
        const float* __restrict__ WlTp, const float* __restrict__ Wlbp,
        float* __restrict__ Wh) {
    constexpr int KP = 256, NC = 16, XDP = 128, CHF = 16 * 384;
    extern __shared__ float sm[];
    float* s_in   = sm;
    float* pool   = sm + KP * 16;
    float* s_gi   = pool + 2 * CHF;
    float* s_preA = pool;
    float* s_preB = pool + GG * 15;
    float* s_out  = pool + GG * 15 + HH * 15;

    const int tid = threadIdx.x;
    const int lane = tid & 31;
    const int grp = tid / 192;
    const int cid = tid % 192;
    const int b0 = blockIdx.x * ROWS;
    const int nrow = min(ROWS, BB - b0);
    unsigned pool_sa = (unsigned)__cvta_generic_to_shared(pool);
    unsigned sgi_sa  = (unsigned)__cvta_generic_to_shared(s_gi);

    {
        const float* gsrc = gi + (size_t)b0 * 384;
        for (int idx = tid; idx < nrow * 96; idx += 384)
            cpa16(sgi_sa + (unsigned)idx * 16u, gsrc + idx * 4);
        #pragma unroll
        for (int v = 0; v < 4; v++) {
            int u = tid + 384 * v;
            cpa16(pool_sa + (unsigned)u * 16u, W + (size_t)u * 4);
        }
        cpa_commit();
    }
    for (int i = tid; i < 127 * ROWS; i += 384) {
        int r = i / 127, k = i % 127;
        s_in[k * 16 + SLOT(r)] = (r < nrow) ? x[(size_t)(b0 + r) * HS + k] : 0.0f;
    }
    for (int i = tid; i < HH * ROWS; i += 384) {
        int r = i / HH, k = i % HH;
        s_in[(XDP + k) * 16 + SLOT(r)] = (r < nrow) ? h_in[(size_t)(b0 + r) * HS + k] : 0.0f;
    }
    for (int i = tid; i < KP * 2; i += 384) {
        int k = i >> 1;
        s_in[k * 16 + ((i & 1) ? 15 : 7)] = 0.0f;
    }
    for (int i = tid; i < 3 * 16; i += 384) {
        int kk = (i / 16 == 0) ? 127 : (XDP + HH + i / 16 - 1);
        s_in[kk * 16 + (i % 16)] = 0.0f;
    }
    cpa_wait0();
    __syncthreads();

    unsigned long long a0[4], a1[4], ax1[4];
    #pragma unroll
    for (int p = 0; p < 4; p++) { a0[p] = dupf(0.0f); a1[p] = dupf(0.0f); ax1[p] = dupf(0.0f); }

    for (int c = 0; c < NC; c++) {
        const int cur = c & 1;
        if (c + 1 < NC) {
            const float* base = W + (size_t)(c + 1) * CHF;
            unsigned dstb = pool_sa + (unsigned)(1 - cur) * CHF * 4u;
            #pragma unroll
            for (int v = 0; v < 4; v++) {
                int u = tid + 384 * v;
                cpa16(dstb + (unsigned)u * 16u, base + (size_t)u * 4);
            }
            cpa_commit();
        }
        const float* wp = pool + cur * CHF + cid;
        const float* ip = s_in + c * 16 * 16 + grp * 8;
        #pragma unroll
        for (int kk = 0; kk < 16; kk++) {
            unsigned long long w0 = dupf(wp[kk * 384]);
            unsigned long long w1 = dupf(wp[kk * 384 + 192]);
            const ulonglong2* sp2 = reinterpret_cast<const ulonglong2*>(ip + kk * 16);
            ulonglong2 q0 = sp2[0], q1 = sp2[1];
            fma2(a0[0], w0, q0.x); fma2(a0[1], w0, q0.y);
            fma2(a0[2], w0, q1.x); fma2(a0[3], w0, q1.y);
            fma2(a1[0], w1, q0.x); fma2(a1[1], w1, q0.y);
            fma2(a1[2], w1, q1.x); fma2(a1[3], w1, q1.y);
        }
        if (c == 7) {
            #pragma unroll
            for (int p = 0; p < 4; p++) ax1[p] = a1[p];
        }
        if (c + 1 < NC) cpa_wait0();
        __syncthreads();
    }

    {
        const int c0 = cid, c1 = cid + 192;
        float f0[8], f1[8], fx1[8];
        #pragma unroll
        for (int p = 0; p < 4; p++) {
            float2 u = unpk(a0[p]); f0[2*p] = u.x; f0[2*p+1] = u.y;
            float2 v = unpk(a1[p]); f1[2*p] = v.x; f1[2*p+1] = v.y;
            float2 w = unpk(ax1[p]); fx1[2*p] = w.x; fx1[2*p+1] = w.y;
        }
        #pragma unroll
        for (int q = 0; q < 7; q++) {
            int r = grp * 7 + q;
            float gv0 = s_gi[r * 384 + c0];
            s_preA[c0 * 15 + r] = f0[q] + gv0;
        }
        if (c1 < GG) {
            #pragma unroll
            for (int q = 0; q < 7; q++) {
                int r = grp * 7 + q;
                float gv1 = s_gi[r * 384 + c1];
                s_preA[c1 * 15 + r] = f1[q] + gv1;
                if (c1 >= 2 * HH) s_preB[(c1 - 2 * HH) * 15 + r] = fx1[q] + gv1;
            }
        }
    }
    if (tid < ROWS) s_out[tid] = 0.0f;
    __syncthreads();

    for (int i = tid; i < ROWS * 128; i += 384) {
        int r = i >> 7;
        int j = i & 127;
        float val = 0.0f;
        if (r < nrow && j < HH) {
            float pr = s_preA[j * 15 + r];
            float pz = s_preA[(HH + j) * 15 + r];
            float nx = s_preB[j * 15 + r];
            float nh = s_preA[(2 * HH + j) * 15 + r] - nx + bhh[2 * HH + j];
            float rg = sigf(pr);
            float zg = sigf(pz);
            float nn = tanhp(nx + rg * nh);
            float hv = s_in[(XDP + j) * 16 + SLOT(r)];
            float hnew = (1.0f - zg) * nn + zg * hv;
            h_out[(size_t)(b0 + r) * HS + j] = hnew;
            s_in[(XDP + j) * 16 + SLOT(r)] = hnew;
            val = hnew * h2oW[j];
        }
        #pragma unroll
        for (int off = 16; off; off >>= 1) val += __shfl_down_sync(0xffffffffu, val, off);
        if (lane == 0 && r < nrow) atomicAdd(&s_out[r], val);
    }
    __syncthreads();
    if (tid < nrow) out[b0 + tid] = s_out[tid] + h2ob[0];

    if (tid < 256) {
        const int j = tid & 127;
        const int g = tid >> 7;
        unsigned long long wa[4];
        #pragma unroll
        for (int p = 0; p < 4; p++) wa[p] = dupf(0.0f);
        #pragma unroll 2
        for (int k = 0; k < HH; k++) {
            unsigned long long wd = dupf(WlTp[k * HS + j]);
            const ulonglong2* sp2 = reinterpret_cast<const ulonglong2*>(s_in + (XDP + k) * 16 + g * 8);
            ulonglong2 q0 = sp2[0], q1 = sp2[1];
            fma2(wa[0], wd, q0.x); fma2(wa[1], wd, q0.y);
            fma2(wa[2], wd, q1.x); fma2(wa[3], wd, q1.y);
        }
        float bj = Wlbp[j];
        float f[8];
        #pragma unroll
        for (int p = 0; p < 4; p++) {
            float2 u = unpk(wa[p]); f[2*p] = u.x; f[2*p+1] = u.y;
        }
        #pragma unroll
        for (int q = 0; q < 7; q++) {
            int r = g * 7 + q;
            if (r < nrow) Wh[(size_t)(b0 + r) * HS + j] = f[q] + bj;
        }
    }
}

// ---------------- dense [rows x 126] @ [126 x 128] + bias (f32x2) ----------
template <bool BF16OUT>
__global__ __launch_bounds__(256, 2) void lin_kernel(const float* __restrict__ in,
                                                     const float* __restrict__ Wp,
                                                     const float* __restrict__ biasp,
                                                     float* __restrict__ outf,
                                                     __nv_bfloat16* __restrict__ outb) {
    constexpr int P2 = 36;
    extern __shared__ float sm[];
    float* s_w  = sm;
    float* s_in = sm + HH * HS;
    const int tid = threadIdx.x;
    const int b0 = blockIdx.x * 32;

    {
        const float4* src = reinterpret_cast<const float4*>(Wp);
        float4* dst = reinterpret_cast<float4*>(s_w);
        for (int v = tid; v < HH * HS / 4; v += 256) dst[v] = src[v];
    }
    for (int idx = tid; idx < HH * 32; idx += 256) {
        int r = idx / HH, k = idx % HH;
        s_in[k * P2 + r] = in[(size_t)(b0 + r) * HS + k];
    }
    __syncthreads();

    const int j = tid & 127;
    const int half = tid >> 7;
    unsigned long long accp[8];
    #pragma unroll
    for (int p = 0; p < 8; p++) accp[p] = dupf(0.0f);
    #pragma unroll 2
    for (int k = 0; k < HH; k++) {
        unsigned long long wd = dupf(s_w[k * HS + j]);
        const ulonglong2* sp2 = reinterpret_cast<const ulonglong2*>(s_in + k * P2 + half * 16);
        ulonglong2 q0 = sp2[0], q1 = sp2[1], q2 = sp2[2], q3 = sp2[3];
        fma2(accp[0], wd, q0.x); fma2(accp[1], wd, q0.y);
        fma2(accp[2], wd, q1.x); fma2(accp[3], wd, q1.y);
        fma2(accp[4], wd, q2.x); fma2(accp[5], wd, q2.y);
        fma2(accp[6], wd, q3.x); fma2(accp[7], wd, q3.y);
    }
    float bj = biasp[j];
    #pragma unroll
    for (int p = 0; p < 8; p++) {
        float2 f = unpk(accp[p]);
        size_t i0 = (size_t)(b0 + half * 16 + 2 * p) * HS + j;
        size_t i1 = (size_t)(b0 + half * 16 + 2 * p + 1) * HS + j;
        if (BF16OUT) {
            outb[i0] = __float2bfloat16(f.x + bj);
            outb[i1] = __float2bfloat16(f.y + bj);
        } else {
            outf[i0] = f.x + bj;
            outf[i1] = f.y + bj;
        }
    }
}

// ---------------- fused attention ----------------
__global__ __launch_bounds__(128) void attn_kernel(
        const __nv_bfloat16* __restrict__ Uobf, const float* __restrict__ Wh,
        const float* __restrict__ Vp, const float* __restrict__ Vb,
        const __nv_bfloat16* __restrict__ encbf,
        const float* __restrict__ enc_data, const float* __restrict__ outbuf,
        float* __restrict__ x, int step) {
    __shared__ float sal[TT * 4];
    const int tid = threadIdx.x;
    const int warp = tid >> 5, lane = tid & 31;
    const int row = blockIdx.x * 4 + warp;

    const float4 wh = *(reinterpret_cast<const float4*>(Wh + (size_t)row * HS) + lane);
    const float4 vv = *(reinterpret_cast<const float4*>(Vp) + lane);
    const float vb = Vb[0];

    #pragma unroll 4
    for (int t = 0; t < TT; t++) {
        uint2 p = *(reinterpret_cast<const uint2*>(Uobf + ((size_t)t * BB + row) * HS) + lane);
        float2 u0 = __bfloat1622float2(*reinterpret_cast<const __nv_bfloat162*>(&p.x));
        float2 u1 = __bfloat1622float2(*reinterpret_cast<const __nv_bfloat162*>(&p.y));
        float a = tanha(u0.x + wh.x) * vv.x + tanha(u0.y + wh.y) * vv.y
                + tanha(u1.x + wh.z) * vv.z + tanha(u1.y + wh.w) * vv.w;
        #pragma unroll
        for (int off = 16; off; off >>= 1) a += __shfl_down_sync(0xffffffffu, a, off);
        if (lane == 0) sal[t * 4 + warp] = a + vb;
    }
    __syncthreads();

    if (tid < 4) {
        float mx = -1e30f;
        for (int t = 0; t < TT; t++) mx = fmaxf(mx, sal[t * 4 + tid]);
        float sum = 0.0f;
        for (int t = 0; t < TT; t++) {
            float e = ex2f((sal[t * 4 + tid] - mx) * LOG2E_);
            sal[t * 4 + tid] = e;
            sum += e;
        }
        float inv = rcpf(sum);
        for (int t = 0; t < TT; t++) sal[t * 4 + tid] *= inv;
    }
    __syncthreads();

    float4 acc = {0.f, 0.f, 0.f, 0.f};
    #pragma unroll 4
    for (int t = 0; t < TT; t++) {
        float al = sal[t * 4 + warp];
        uint2 p = *(reinterpret_cast<const uint2*>(encbf + ((size_t)t * BB + row) * HS) + lane);
        float2 e0 = __bfloat1622float2(*reinterpret_cast<const __nv_bfloat162*>(&p.x));
        float2 e1 = __bfloat1622float2(*reinterpret_cast<const __nv_bfloat162*>(&p.y));
        acc.x += al * e0.x; acc.y += al * e0.y; acc.z += al * e1.x; acc.w += al * e1.y;
    }
    float* xr = x + (size_t)row * HS;
    if (lane < 31) {
        *(reinterpret_cast<float4*>(xr) + lane) = acc;
    } else {
        xr[124] = acc.x;
        xr[125] = acc.y;
    }
    if (lane == 0) {
        float prev = (step == 0) ? enc_data[((size_t)(TT - 1) * BB + row) * ENC_]
                                 : outbuf[(size_t)(step - 1) * BB + row];
        xr[126] = prev;
    }
}

// ---------------- host side ----------------
extern "C" void kernel_launch(void* const* d_in, const int* in_sizes, int n_in,
                              void* d_out, int out_size) {
    const float* ann      = (const float*)d_in[0];
    const float* enc_data = (const float*)d_in[1];
    const float* dec_data = (const float*)d_in[2];
    const float* s2h_W1   = (const float*)d_in[3];
    const float* s2h_b1   = (const float*)d_in[4];
    const float* s2h_W2   = (const float*)d_in[5];
    const float* s2h_b2   = (const float*)d_in[6];
    const float* enc_Wih  = (const float*)d_in[7];
    const float* enc_Whh  = (const float*)d_in[8];
    const float* enc_bih  = (const float*)d_in[9];
    const float* enc_bhh  = (const float*)d_in[10];
    const float* dec_Wih  = (const float*)d_in[11];
    const float* dec_Whh  = (const float*)d_in[12];
    const float* dec_bih  = (const float*)d_in[13];
    const float* dec_bhh  = (const float*)d_in[14];
    const float* U_W      = (const float*)d_in[15];
    const float* U_b      = (const float*)d_in[16];
    const float* Wl_W     = (const float*)d_in[17];
    const float* Wl_b     = (const float*)d_in[18];
    const float* V_W      = (const float*)d_in[19];
    const float* V_b      = (const float*)d_in[20];
    const float* h2o_W    = (const float*)d_in[21];
    const float* h2o_b    = (const float*)d_in[22];
    float* outp = (float*)d_out;

    float *h0, *h1, *enc_out, *Wh, *x, *giE, *giD;
    float *Wenc, *Wdec, *WgiE, *WgiD, *bgE, *bgD, *UWTp, *WlTp, *Ubp, *Wlbp, *Vp;
    __nv_bfloat16 *Uobf, *encbf;
    cudaGetSymbolAddress((void**)&h0, g_h0);
    cudaGetSymbolAddress((void**)&h1, g_h1);
    cudaGetSymbolAddress((void**)&enc_out, g_enc_out);
    cudaGetSymbolAddress((void**)&encbf, g_enc_bf);
    cudaGetSymbolAddress((void**)&Uobf, g_Uobf);
    cudaGetSymbolAddress((void**)&Wh, g_Wh);
    cudaGetSymbolAddress((void**)&x, g_x);
    cudaGetSymbolAddress((void**)&giE, g_giE);
    cudaGetSymbolAddress((void**)&giD, g_giD);
    cudaGetSymbolAddress((void**)&Wenc, g_Wenc);
    cudaGetSymbolAddress((void**)&Wdec, g_Wdec);
    cudaGetSymbolAddress((void**)&WgiE, g_WgiE);
    cudaGetSymbolAddress((void**)&WgiD, g_WgiD);
    cudaGetSymbolAddress((void**)&bgE, g_bgE);
    cudaGetSymbolAddress((void**)&bgD, g_bgD);
    cudaGetSymbolAddress((void**)&UWTp, g_UWTp);
    cudaGetSymbolAddress((void**)&WlTp, g_WlTp);
    cudaGetSymbolAddress((void**)&Ubp, g_Ubp);
    cudaGetSymbolAddress((void**)&Wlbp, g_Wlbp);
    cudaGetSymbolAddress((void**)&Vp, g_Vp);

    const size_t sm_enc = (size_t)(128 * 16 + 2 * 16 * 384 + ROWS * 384) * 4;  // 78848
    const size_t sm_dec = (size_t)(256 * 16 + 2 * 16 * 384 + ROWS * 384) * 4;  // 87040
    const size_t sm_uo  = (size_t)(HH * HS + HH * 36) * 4;
    cudaFuncSetAttribute((const void*)gruE_all_kernel,
                         cudaFuncAttributeMaxDynamicSharedMemorySize, (int)sm_enc);
    cudaFuncSetAttribute((const void*)gruD_kernel,
                         cudaFuncAttributeMaxDynamicSharedMemorySize, (int)sm_dec);
    cudaFuncSetAttribute((const void*)lin_kernel<false>,
                         cudaFuncAttributeMaxDynamicSharedMemorySize, (int)sm_uo);
    cudaFuncSetAttribute((const void*)lin_kernel<true>,
                         cudaFuncAttributeMaxDynamicSharedMemorySize, (int)sm_uo);

    const int total_w = 128 * 384 + 256 * 384 + ENC_ * 384 + DEC_ * 384 + 384
                      + 2 * HH * HS + 3 * HS;
    prep_weights<<<(total_w + 255) / 256, 256>>>(enc_Wih, enc_Whh, dec_Wih, dec_Whh,
                                                 U_W, U_b, Wl_W, Wl_b, V_W,
                                                 enc_bih, enc_bhh, dec_bih, dec_bhh);

    s2h_kernel<<<BB, 128>>>(ann, s2h_W1, s2h_b1, s2h_W2, s2h_b2, h0);

    gi_kernel<ENC_><<<TT * BB / 16, 384>>>(enc_data, WgiE, bgE, giE);

    // persistent encoder: all 56 steps, one launch
    gruE_all_kernel<<<NBLK, 384, sm_enc>>>(h0, Wenc, giE, enc_bhh, enc_out, encbf);

    gi_kernel<DEC_><<<NSTEPS * BB / 16, 384>>>(dec_data, WgiD, bgD, giD);

    lin_kernel<true><<<TT * BB / 32, 256, sm_uo>>>(enc_out, UWTp, Ubp, nullptr, Uobf);

    const float* enc_last = enc_out + (size_t)(TT - 1) * BB * HS;
    lin_kernel<false><<<BB / 32, 256, sm_uo>>>(enc_last, WlTp, Wlbp, Wh, nullptr);

    for (int s = 0; s < NSTEPS; s++) {
        const float* hcur = (s == 0) ? enc_last : ((s & 1) ? h0 : h1);
        float* hnext      = (s & 1) ? h1 : h0;
        attn_kernel<<<BB / 4, 128>>>(Uobf, Wh, Vp, V_b, encbf, enc_data, outp, x, s);
        gruD_kernel<<<NBLK, 384, sm_dec>>>(
            hcur, x, Wdec, giD + (size_t)s * BB * 384, dec_bhh, hnext,
            h2o_W, h2o_b, outp + (size_t)s * BB, WlTp, Wlbp, Wh);
    }
}

// round 17
// speedup vs baseline: 1.1306x; 1.0401x over previous
#include <cuda_runtime.h>
#include <cuda_bf16.h>
#include <cstdint>
#include <math.h>

#define BB     4096
#define TT     56
#define NSTEPS 28
#define HH     126
#define GG     378
#define ANN_   30
#define ENC_   20
#define DEC_   15

#define HS     128
#define ROWS   14
#define NBLK   ((BB + ROWS - 1) / ROWS)   // 293

#define SLOT(r) ((r) + ((r) >= 7 ? 1 : 0))

// ---------------- scratch ----------------
__device__ float g_h0[BB * HS];
__device__ float g_enc_out[TT * BB * HS];
__device__ __nv_bfloat16 g_enc_bf[(size_t)TT * BB * HS];
__device__ __nv_bfloat16 g_Uobf[(size_t)TT * BB * HS];
__device__ float g_giE[(size_t)TT * BB * 384];
__device__ float g_giD[(size_t)NSTEPS * BB * 384];
__device__ float g_Wenc[128 * 384];
__device__ float g_Wdec[256 * 384];
__device__ float g_WgiE[ENC_ * 384];
__device__ float g_WgiD[DEC_ * 384];
__device__ float g_bgE[384];
__device__ float g_bgD[384];
__device__ float g_UWTp[HH * HS];
__device__ float g_WlTp[HH * HS];
__device__ float g_Ubp[HS];
__device__ float g_Wlbp[HS];
__device__ float g_Vp[HS];

// ---------------- fast transcendentals ----------------
__device__ __forceinline__ float ex2f(float x) { float y; asm("ex2.approx.f32 %0, %1;" : "=f"(y) : "f"(x)); return y; }
__device__ __forceinline__ float rcpf(float x) { float y; asm("rcp.approx.f32 %0, %1;" : "=f"(y) : "f"(x)); return y; }
__device__ __forceinline__ float tanha(float x) { float y; asm("tanh.approx.f32 %0, %1;" : "=f"(y) : "f"(x)); return y; }
#define LOG2E_ 1.4426950408889634f
__device__ __forceinline__ float sigf(float v)  { return rcpf(1.0f + ex2f(-v * LOG2E_)); }
__device__ __forceinline__ float tanhp(float v) { return 2.0f * rcpf(1.0f + ex2f(-2.0f * v * LOG2E_)) - 1.0f; }

// ---------------- packed f32x2 FMA ----------------
__device__ __forceinline__ unsigned long long dupf(float w) {
    unsigned long long r; asm("mov.b64 %0, {%1, %1};" : "=l"(r) : "f"(w)); return r;
}
__device__ __forceinline__ void fma2(unsigned long long& d, unsigned long long a, unsigned long long b) {
    asm("fma.rn.f32x2 %0, %1, %2, %0;" : "+l"(d) : "l"(a), "l"(b));
}
__device__ __forceinline__ float2 unpk(unsigned long long v) {
    float2 f; asm("mov.b64 {%0, %1}, %2;" : "=f"(f.x), "=f"(f.y) : "l"(v)); return f;
}

// ---------------- cp.async ----------------
__device__ __forceinline__ void cpa16(unsigned dst, const void* src) {
    asm volatile("cp.async.cg.shared.global [%0], [%1], 16;" :: "r"(dst), "l"(src));
}
__device__ __forceinline__ void cpa_commit() { asm volatile("cp.async.commit_group;"); }
__device__ __forceinline__ void cpa_wait0()  { asm volatile("cp.async.wait_group 0;"); }

// ---------------- weight prep ----------------
__global__ void prep_weights(const float* __restrict__ eWih, const float* __restrict__ eWhh,
                             const float* __restrict__ dWih, const float* __restrict__ dWhh,
                             const float* __restrict__ U,    const float* __restrict__ Ub,
                             const float* __restrict__ Wl,   const float* __restrict__ Wlb,
                             const float* __restrict__ V,
                             const float* __restrict__ ebih, const float* __restrict__ ebhh,
                             const float* __restrict__ dbih, const float* __restrict__ dbhh) {
    int i = blockIdx.x * 256 + threadIdx.x;
    const int Nwe = 128 * 384, Nwd = 256 * 384, Nge = ENC_ * 384, Ngd = DEC_ * 384;
    const int Nuw = HH * HS;
    if (i < Nwe) {
        int k = i / 384, j = i % 384;
        g_Wenc[i] = (j < GG && k < HH) ? eWhh[j * HH + k] : 0.0f;
        return;
    }
    i -= Nwe;
    if (i < Nwd) {
        int k = i / 384, j = i % 384;
        float v = 0.0f;
        if (j < GG) {
            if (k < 126) v = dWih[j * 142 + 16 + k];
            else if (k == 126) v = dWih[j * 142 + 0];
            else if (k >= 128 && k < 254) v = dWhh[j * HH + (k - 128)];
        }
        g_Wdec[i] = v; return;
    }
    i -= Nwd;
    if (i < Nge) {
        int k = i / 384, j = i % 384;
        g_WgiE[i] = (j < GG) ? eWih[j * ENC_ + k] : 0.0f;
        return;
    }
    i -= Nge;
    if (i < Ngd) {
        int k = i / 384, j = i % 384;
        g_WgiD[i] = (j < GG) ? dWih[j * 142 + 1 + k] : 0.0f;
        return;
    }
    i -= Ngd;
    if (i < 384) {
        g_bgE[i] = (i < GG) ? (ebih[i] + ((i < 2 * HH) ? ebhh[i] : 0.0f)) : 0.0f;
        g_bgD[i] = (i < GG) ? (dbih[i] + ((i < 2 * HH) ? dbhh[i] : 0.0f)) : 0.0f;
        return;
    }
    i -= 384;
    if (i < Nuw) { int k = i / HS, j = i % HS; g_UWTp[i] = (j < HH) ? U[j * HH + k] : 0.0f; return; }
    i -= Nuw;
    if (i < Nuw) { int k = i / HS, j = i % HS; g_WlTp[i] = (j < HH) ? Wl[j * HH + k] : 0.0f; return; }
    i -= Nuw;
    if (i < HS) { g_Ubp[i] = (i < HH) ? Ub[i] : 0.0f; return; }
    i -= HS;
    if (i < HS) { g_Wlbp[i] = (i < HH) ? Wlb[i] : 0.0f; return; }
    i -= HS;
    if (i < HS) { g_Vp[i] = (i < HH) ? V[i] : 0.0f; }
}

// ---------------- s2h MLP ----------------
__global__ void s2h_kernel(const float* __restrict__ ann,
                           const float* __restrict__ W1, const float* __restrict__ b1,
                           const float* __restrict__ W2, const float* __restrict__ b2,
                           float* __restrict__ h) {
    __shared__ float a[ANN_];
    __shared__ float mid[96];
    int b = blockIdx.x;
    int tid = threadIdx.x;
    if (tid < ANN_) a[tid] = ann[b * ANN_ + tid];
    __syncthreads();
    if (tid < 96) {
        float acc = b1[tid];
        #pragma unroll
        for (int k = 0; k < ANN_; k++) acc += W1[tid * ANN_ + k] * a[k];
        mid[tid] = fmaxf(acc, 0.0f);
    }
    __syncthreads();
    if (tid < HH) {
        float acc = b2[tid];
        #pragma unroll 4
        for (int k = 0; k < 96; k++) acc += W2[tid * 96 + k] * mid[k];
        h[(size_t)b * HS + tid] = acc;
    }
}

// ---------------- gi GEMM (bias folded, f32x2) ----------------
template <int KD>
__global__ __launch_bounds__(384) void gi_kernel(const float* __restrict__ in,
                                                 const float* __restrict__ Wg,
                                                 const float* __restrict__ bg,
                                                 float* __restrict__ gi) {
    __shared__ float s_w[KD * 384];
    __shared__ float s_in[KD * 16];
    const int tid = threadIdx.x;
    const int b0 = blockIdx.x * 16;
    for (int i = tid; i < KD * 96; i += 384)
        reinterpret_cast<float4*>(s_w)[i] = reinterpret_cast<const float4*>(Wg)[i];
    for (int i = tid; i < KD * 16; i += 384) {
        int r = i / KD, k = i % KD;
        s_in[k * 16 + r] = in[(size_t)(b0 + r) * KD + k];
    }
    __syncthreads();
    unsigned long long accp[8];
    #pragma unroll
    for (int p = 0; p < 8; p++) accp[p] = dupf(0.0f);
    #pragma unroll 4
    for (int k = 0; k < KD; k++) {
        unsigned long long wd = dupf(s_w[k * 384 + tid]);
        const ulonglong2* sp2 = reinterpret_cast<const ulonglong2*>(s_in + k * 16);
        ulonglong2 q0 = sp2[0], q1 = sp2[1], q2 = sp2[2], q3 = sp2[3];
        fma2(accp[0], wd, q0.x); fma2(accp[1], wd, q0.y);
        fma2(accp[2], wd, q1.x); fma2(accp[3], wd, q1.y);
        fma2(accp[4], wd, q2.x); fma2(accp[5], wd, q2.y);
        fma2(accp[6], wd, q3.x); fma2(accp[7], wd, q3.y);
    }
    float bb = bg[tid];
    #pragma unroll
    for (int p = 0; p < 8; p++) {
        float2 f = unpk(accp[p]);
        gi[(size_t)(b0 + 2 * p) * 384 + tid]     = f.x + bb;
        gi[(size_t)(b0 + 2 * p + 1) * 384 + tid] = f.y + bb;
    }
}

// ---------------- PERSISTENT encoder (unchanged from R16) ------------------
__global__ __launch_bounds__(384, 2) void gruE_all_kernel(
        const float* __restrict__ h0,
        const float* __restrict__ W,
        const float* __restrict__ giE,
        const float* __restrict__ bhh,
        float* __restrict__ enc_out,
        __nv_bfloat16* __restrict__ enc_bf) {
    constexpr int KP = 128, NC = 8, CHF = 16 * 384;
    extern __shared__ float sm[];
    float* s_in   = sm;
    float* pool   = sm + KP * 16;
    float* s_gi   = pool + 2 * CHF;
    float* s_preA = pool;
    float* s_preB = pool + GG * 15;

    const int tid = threadIdx.x;
    const int grp = tid / 192;
    const int cid = tid % 192;
    const int b0 = blockIdx.x * ROWS;
    const int nrow = min(ROWS, BB - b0);
    unsigned pool_sa = (unsigned)__cvta_generic_to_shared(pool);
    unsigned sgi_sa  = (unsigned)__cvta_generic_to_shared(s_gi);

    for (int i = tid; i < HH * ROWS; i += 384) {
        int r = i / HH, k = i % HH;
        s_in[k * 16 + SLOT(r)] = (r < nrow) ? h0[(size_t)(b0 + r) * HS + k] : 0.0f;
    }
    for (int i = tid; i < KP * 2; i += 384) {
        int k = i >> 1;
        s_in[k * 16 + ((i & 1) ? 15 : 7)] = 0.0f;
    }
    for (int i = tid; i < 2 * 16; i += 384)
        s_in[(HH + i / 16) * 16 + (i % 16)] = 0.0f;
    __syncthreads();

    for (int t = 0; t < TT; t++) {
        {
            const float* gsrc = giE + ((size_t)t * BB + b0) * 384;
            for (int idx = tid; idx < nrow * 96; idx += 384)
                cpa16(sgi_sa + (unsigned)idx * 16u, gsrc + idx * 4);
            #pragma unroll
            for (int v = 0; v < 4; v++) {
                int u = tid + 384 * v;
                cpa16(pool_sa + (unsigned)u * 16u, W + (size_t)u * 4);
            }
            cpa_commit();
        }
        cpa_wait0();
        __syncthreads();

        unsigned long long a0[4], a1[4];
        #pragma unroll
        for (int p = 0; p < 4; p++) { a0[p] = dupf(0.0f); a1[p] = dupf(0.0f); }

        for (int c = 0; c < NC; c++) {
            const int cur = c & 1;
            if (c + 1 < NC) {
                const float* base = W + (size_t)(c + 1) * CHF;
                unsigned dstb = pool_sa + (unsigned)(1 - cur) * CHF * 4u;
                #pragma unroll
                for (int v = 0; v < 4; v++) {
                    int u = tid + 384 * v;
                    cpa16(dstb + (unsigned)u * 16u, base + (size_t)u * 4);
                }
                cpa_commit();
            }
            const float* wp = pool + cur * CHF + cid;
            const float* ip = s_in + c * 16 * 16 + grp * 8;
            #pragma unroll
            for (int kk = 0; kk < 16; kk++) {
                unsigned long long w0 = dupf(wp[kk * 384]);
                unsigned long long w1 = dupf(wp[kk * 384 + 192]);
                const ulonglong2* sp2 = reinterpret_cast<const ulonglong2*>(ip + kk * 16);
                ulonglong2 q0 = sp2[0], q1 = sp2[1];
                fma2(a0[0], w0, q0.x); fma2(a0[1], w0, q0.y);
                fma2(a0[2], w0, q1.x); fma2(a0[3], w0, q1.y);
                fma2(a1[0], w1, q0.x); fma2(a1[1], w1, q0.y);
                fma2(a1[2], w1, q1.x); fma2(a1[3], w1, q1.y);
            }
            if (c + 1 < NC) cpa_wait0();
            __syncthreads();
        }

        {
            const int c0 = cid, c1 = cid + 192;
            float f0[8], f1[8];
            #pragma unroll
            for (int p = 0; p < 4; p++) {
                float2 u = unpk(a0[p]); f0[2*p] = u.x; f0[2*p+1] = u.y;
                float2 v = unpk(a1[p]); f1[2*p] = v.x; f1[2*p+1] = v.y;
            }
            #pragma unroll
            for (int q = 0; q < 7; q++) {
                int r = grp * 7 + q;
                s_preA[c0 * 15 + r] = f0[q] + s_gi[r * 384 + c0];
            }
            if (c1 < GG) {
                #pragma unroll
                for (int q = 0; q < 7; q++) {
                    int r = grp * 7 + q;
                    float gv1 = s_gi[r * 384 + c1];
                    s_preA[c1 * 15 + r] = f1[q] + gv1;
                    if (c1 >= 2 * HH) s_preB[(c1 - 2 * HH) * 15 + r] = gv1;
                }
            }
        }
        __syncthreads();

        float* eo = enc_out + (size_t)t * BB * HS;
        __nv_bfloat16* eb = enc_bf + (size_t)t * BB * HS;
        for (int i = tid; i < ROWS * 128; i += 384) {
            int r = i >> 7;
            int j = i & 127;
            if (r >= nrow) continue;
            size_t oidx = (size_t)(b0 + r) * HS + j;
            if (j < HH) {
                float pr = s_preA[j * 15 + r];
                float pz = s_preA[(HH + j) * 15 + r];
                float nx = s_preB[j * 15 + r];
                float nh = s_preA[(2 * HH + j) * 15 + r] - nx + bhh[2 * HH + j];
                float rg = sigf(pr);
                float zg = sigf(pz);
                float nn = tanhp(nx + rg * nh);
                float hv = s_in[j * 16 + SLOT(r)];
                float hnew = (1.0f - zg) * nn + zg * hv;
                s_in[j * 16 + SLOT(r)] = hnew;
                eo[oidx] = hnew;
                eb[oidx] = __float2bfloat16(hnew);
            } else {
                eo[oidx] = 0.0f;
                eb[oidx] = __float2bfloat16(0.0f);
            }
        }
        __syncthreads();
    }
}

// ---------------- PERSISTENT decoder: all 28 steps, one launch -------------
// 448 threads = 14 warps (warp-per-row attention); GEMM uses threads 0..383.
__global__ __launch_bounds__(448, 2) void gruD_all_kernel(
        const float* __restrict__ h_init,
        const float* __restrict__ W,      // [256][384]
        const float* __restrict__ giD,    // [s][row][384]
        const float* __restrict__ bhh,
        const __nv_bfloat16* __restrict__ Uobf,
        const __nv_bfloat16* __restrict__ encbf,
        const float* __restrict__ WlTp, const float* __restrict__ Wlbp,
        const float* __restrict__ Vp, const float* __restrict__ Vb,
        const float* __restrict__ enc_data,
        const float* __restrict__ h2oW, const float* __restrict__ h2ob,
        float* __restrict__ outp) {
    constexpr int KP = 256, NC = 16, XDP = 128, CHF = 16 * 384;
    extern __shared__ float sm[];
    float* s_in   = sm;                       // 256*16 = 4096
    float* pool   = sm + KP * 16;             // 2*CHF = 12288
    float* s_gi   = pool + 2 * CHF;           // 14*384 = 5376
    float* s_wh   = s_gi + ROWS * 384;        // 14*132 = 1848
    float* sal    = s_wh + ROWS * 132;        // 56*14 = 784
    float* s_prev = sal + TT * ROWS;          // 14
    float* s_preA = pool;                     // aliases pool after GEMM
    float* s_preB = pool + GG * 15;
    float* s_out  = pool + GG * 15 + HH * 15;

    const int tid = threadIdx.x;
    const int warp = tid >> 5, lane = tid & 31;
    const int b0 = blockIdx.x * ROWS;
    const int nrow = min(ROWS, BB - b0);
    unsigned pool_sa = (unsigned)__cvta_generic_to_shared(pool);
    unsigned sgi_sa  = (unsigned)__cvta_generic_to_shared(s_gi);

    // init: zero s_in (covers x region, pads, slots 7/15), then load h
    for (int i = tid; i < KP * 16; i += 448) s_in[i] = 0.0f;
    __syncthreads();
    for (int i = tid; i < HH * ROWS; i += 448) {
        int r = i / HH, k = i % HH;
        if (r < nrow) s_in[(XDP + k) * 16 + SLOT(r)] = h_init[(size_t)(b0 + r) * HS + k];
    }
    if (tid < nrow)
        s_prev[tid] = enc_data[((size_t)(TT - 1) * BB + b0 + tid) * ENC_];
    __syncthreads();

    for (int s = 0; s < NSTEPS; s++) {
        // prefetch gi + weight chunk 0 (lands during attention phases)
        {
            const float* gsrc = giD + ((size_t)s * BB + b0) * 384;
            for (int idx = tid; idx < nrow * 96; idx += 448)
                cpa16(sgi_sa + (unsigned)idx * 16u, gsrc + idx * 4);
            for (int u = tid; u < 1536; u += 448)
                cpa16(pool_sa + (unsigned)u * 16u, W + (size_t)u * 4);
            cpa_commit();
        }

        // Phase W: Wh = h @ Wl^T + b  (256 threads)
        if (tid < 256) {
            const int j = tid & 127;
            const int g = tid >> 7;
            unsigned long long wa[4];
            #pragma unroll
            for (int p = 0; p < 4; p++) wa[p] = dupf(0.0f);
            #pragma unroll 2
            for (int k = 0; k < HH; k++) {
                unsigned long long wd = dupf(WlTp[k * HS + j]);
                const ulonglong2* sp2 = reinterpret_cast<const ulonglong2*>(s_in + (XDP + k) * 16 + g * 8);
                ulonglong2 q0 = sp2[0], q1 = sp2[1];
                fma2(wa[0], wd, q0.x); fma2(wa[1], wd, q0.y);
                fma2(wa[2], wd, q1.x); fma2(wa[3], wd, q1.y);
            }
            float bj = Wlbp[j];
            float f[8];
            #pragma unroll
            for (int p = 0; p < 4; p++) {
                float2 u = unpk(wa[p]); f[2*p] = u.x; f[2*p+1] = u.y;
            }
            #pragma unroll
            for (int q = 0; q < 7; q++)
                s_wh[(g * 7 + q) * 132 + j] = f[q] + bj;
        }
        __syncthreads();

        // Phase S: scores, warp-per-row
        if (warp < ROWS && warp < nrow) {
            const int r = warp;
            const float4 wh = *(reinterpret_cast<const float4*>(s_wh + r * 132) + lane);
            const float4 vv = *(reinterpret_cast<const float4*>(Vp) + lane);
            const float vb = Vb[0];
            #pragma unroll 4
            for (int t = 0; t < TT; t++) {
                uint2 p = *(reinterpret_cast<const uint2*>(Uobf + ((size_t)t * BB + b0 + r) * HS) + lane);
                float2 u0 = __bfloat1622float2(*reinterpret_cast<const __nv_bfloat162*>(&p.x));
                float2 u1 = __bfloat1622float2(*reinterpret_cast<const __nv_bfloat162*>(&p.y));
                float a = tanha(u0.x + wh.x) * vv.x + tanha(u0.y + wh.y) * vv.y
                        + tanha(u1.x + wh.z) * vv.z + tanha(u1.y + wh.w) * vv.w;
                #pragma unroll
                for (int off = 16; off; off >>= 1) a += __shfl_down_sync(0xffffffffu, a, off);
                if (lane == 0) sal[t * ROWS + r] = a + vb;
            }
        }
        __syncthreads();

        // Phase M: softmax over t per row
        if (tid < nrow) {
            float mx = -1e30f;
            for (int t = 0; t < TT; t++) mx = fmaxf(mx, sal[t * ROWS + tid]);
            float sum = 0.0f;
            for (int t = 0; t < TT; t++) {
                float e = ex2f((sal[t * ROWS + tid] - mx) * LOG2E_);
                sal[t * ROWS + tid] = e;
                sum += e;
            }
            float inv = rcpf(sum);
            for (int t = 0; t < TT; t++) sal[t * ROWS + tid] *= inv;
        }
        __syncthreads();

        // Phase C: context -> s_in x cols 0..125; col 126 = prev (exclusive owner)
        if (warp < ROWS && warp < nrow) {
            const int r = warp;
            float4 acc = {0.f, 0.f, 0.f, 0.f};
            #pragma unroll 4
            for (int t = 0; t < TT; t++) {
                float al = sal[t * ROWS + r];
                uint2 p = *(reinterpret_cast<const uint2*>(encbf + ((size_t)t * BB + b0 + r) * HS) + lane);
                float2 e0 = __bfloat1622float2(*reinterpret_cast<const __nv_bfloat162*>(&p.x));
                float2 e1 = __bfloat1622float2(*reinterpret_cast<const __nv_bfloat162*>(&p.y));
                acc.x += al * e0.x; acc.y += al * e0.y; acc.z += al * e1.x; acc.w += al * e1.y;
            }
            int sl = SLOT(r);
            s_in[(4 * lane + 0) * 16 + sl] = acc.x;
            s_in[(4 * lane + 1) * 16 + sl] = acc.y;
            if (lane < 31) {
                s_in[(4 * lane + 2) * 16 + sl] = acc.z;
                s_in[(4 * lane + 3) * 16 + sl] = acc.w;
            }
        }
        if (tid < nrow) s_in[126 * 16 + SLOT(tid)] = s_prev[tid];
        cpa_wait0();
        __syncthreads();

        // Phase G: GEMM (threads 0..383)
        unsigned long long a0[4], a1[4], ax1[4];
        #pragma unroll
        for (int p = 0; p < 4; p++) { a0[p] = dupf(0.0f); a1[p] = dupf(0.0f); ax1[p] = dupf(0.0f); }
        const int grp = (tid < 384) ? tid / 192 : 0;
        const int cid = (tid < 384) ? tid % 192 : 0;

        for (int c = 0; c < NC; c++) {
            const int cur = c & 1;
            if (c + 1 < NC) {
                const float* base = W + (size_t)(c + 1) * CHF;
                unsigned dstb = pool_sa + (unsigned)(1 - cur) * CHF * 4u;
                for (int u = tid; u < 1536; u += 448)
                    cpa16(dstb + (unsigned)u * 16u, base + (size_t)u * 4);
                cpa_commit();
            }
            if (tid < 384) {
                const float* wp = pool + cur * CHF + cid;
                const float* ip = s_in + c * 16 * 16 + grp * 8;
                #pragma unroll
                for (int kk = 0; kk < 16; kk++) {
                    unsigned long long w0 = dupf(wp[kk * 384]);
                    unsigned long long w1 = dupf(wp[kk * 384 + 192]);
                    const ulonglong2* sp2 = reinterpret_cast<const ulonglong2*>(ip + kk * 16);
                    ulonglong2 q0 = sp2[0], q1 = sp2[1];
                    fma2(a0[0], w0, q0.x); fma2(a0[1], w0, q0.y);
                    fma2(a0[2], w0, q1.x); fma2(a0[3], w0, q1.y);
                    fma2(a1[0], w1, q0.x); fma2(a1[1], w1, q0.y);
                    fma2(a1[2], w1, q1.x); fma2(a1[3], w1, q1.y);
                }
            }
            if (c == 7) {
                #pragma unroll
                for (int p = 0; p < 4; p++) ax1[p] = a1[p];
            }
            if (c + 1 < NC) cpa_wait0();
            __syncthreads();
        }

        // preacts into pool
        if (tid < 384) {
            const int c0 = cid, c1 = cid + 192;
            float f0[8], f1[8], fx1[8];
            #pragma unroll
            for (int p = 0; p < 4; p++) {
                float2 u = unpk(a0[p]); f0[2*p] = u.x; f0[2*p+1] = u.y;
                float2 v = unpk(a1[p]); f1[2*p] = v.x; f1[2*p+1] = v.y;
                float2 w = unpk(ax1[p]); fx1[2*p] = w.x; fx1[2*p+1] = w.y;
            }
            #pragma unroll
            for (int q = 0; q < 7; q++) {
                int r = grp * 7 + q;
                s_preA[c0 * 15 + r] = f0[q] + s_gi[r * 384 + c0];
            }
            if (c1 < GG) {
                #pragma unroll
                for (int q = 0; q < 7; q++) {
                    int r = grp * 7 + q;
                    float gv1 = s_gi[r * 384 + c1];
                    s_preA[c1 * 15 + r] = f1[q] + gv1;
                    if (c1 >= 2 * HH) s_preB[(c1 - 2 * HH) * 15 + r] = fx1[q] + gv1;
                }
            }
        }
        if (tid < ROWS) s_out[tid] = 0.0f;
        __syncthreads();

        // gates + h2o
        for (int i = tid; i < ROWS * 128; i += 448) {
            int r = i >> 7;
            int j = i & 127;
            float val = 0.0f;
            if (r < nrow && j < HH) {
                float pr = s_preA[j * 15 + r];
                float pz = s_preA[(HH + j) * 15 + r];
                float nx = s_preB[j * 15 + r];
                float nh = s_preA[(2 * HH + j) * 15 + r] - nx + bhh[2 * HH + j];
                float rg = sigf(pr);
                float zg = sigf(pz);
                float nn = tanhp(nx + rg * nh);
                float hv = s_in[(XDP + j) * 16 + SLOT(r)];
                float hnew = (1.0f - zg) * nn + zg * hv;
                s_in[(XDP + j) * 16 + SLOT(r)] = hnew;
                val = hnew * h2oW[j];
            }
            #pragma unroll
            for (int off = 16; off; off >>= 1) val += __shfl_down_sync(0xffffffffu, val, off);
            if (lane == 0 && r < nrow) atomicAdd(&s_out[r], val);
        }
        __syncthreads();
        if (tid < nrow) {
            float o = s_out[tid] + h2ob[0];
            outp[(size_t)s * BB + b0 + tid] = o;
            s_prev[tid] = o;
        }
        __syncthreads();   // protect pool/s_prev before next step's prefetch
    }
}

// ---------------- Uo = enc_out @ U^T + b, bf16 out (f32x2) ------------------
__global__ __launch_bounds__(256, 2) void uo_kernel(const float* __restrict__ in,
                                                    const float* __restrict__ Wp,
                                                    const float* __restrict__ biasp,
                                                    __nv_bfloat16* __restrict__ outb) {
    constexpr int P2 = 36;
    extern __shared__ float sm[];
    float* s_w  = sm;
    float* s_in = sm + HH * HS;
    const int tid = threadIdx.x;
    const int b0 = blockIdx.x * 32;

    {
        const float4* src = reinterpret_cast<const float4*>(Wp);
        float4* dst = reinterpret_cast<float4*>(s_w);
        for (int v = tid; v < HH * HS / 4; v += 256) dst[v] = src[v];
    }
    for (int idx = tid; idx < HH * 32; idx += 256) {
        int r = idx / HH, k = idx % HH;
        s_in[k * P2 + r] = in[(size_t)(b0 + r) * HS + k];
    }
    __syncthreads();

    const int j = tid & 127;
    const int half = tid >> 7;
    unsigned long long accp[8];
    #pragma unroll
    for (int p = 0; p < 8; p++) accp[p] = dupf(0.0f);
    #pragma unroll 2
    for (int k = 0; k < HH; k++) {
        unsigned long long wd = dupf(s_w[k * HS + j]);
        const ulonglong2* sp2 = reinterpret_cast<const ulonglong2*>(s_in + k * P2 + half * 16);
        ulonglong2 q0 = sp2[0], q1 = sp2[1], q2 = sp2[2], q3 = sp2[3];
        fma2(accp[0], wd, q0.x); fma2(accp[1], wd, q0.y);
        fma2(accp[2], wd, q1.x); fma2(accp[3], wd, q1.y);
        fma2(accp[4], wd, q2.x); fma2(accp[5], wd, q2.y);
        fma2(accp[6], wd, q3.x); fma2(accp[7], wd, q3.y);
    }
    float bj = biasp[j];
    #pragma unroll
    for (int p = 0; p < 8; p++) {
        float2 f = unpk(accp[p]);
        outb[(size_t)(b0 + half * 16 + 2 * p) * HS + j]     = __float2bfloat16(f.x + bj);
        outb[(size_t)(b0 + half * 16 + 2 * p + 1) * HS + j] = __float2bfloat16(f.y + bj);
    }
}

// ---------------- host side ----------------
extern "C" void kernel_launch(void* const* d_in, const int* in_sizes, int n_in,
                              void* d_out, int out_size) {
    const float* ann      = (const float*)d_in[0];
    const float* enc_data = (const float*)d_in[1];
    const float* dec_data = (const float*)d_in[2];
    const float* s2h_W1   = (const float*)d_in[3];
    const float* s2h_b1   = (const float*)d_in[4];
    const float* s2h_W2   = (const float*)d_in[5];
    const float* s2h_b2   = (const float*)d_in[6];
    const float* enc_Wih  = (const float*)d_in[7];
    const float* enc_Whh  = (const float*)d_in[8];
    const float* enc_bih  = (const float*)d_in[9];
    const float* enc_bhh  = (const float*)d_in[10];
    const float* dec_Wih  = (const float*)d_in[11];
    const float* dec_Whh  = (const float*)d_in[12];
    const float* dec_bih  = (const float*)d_in[13];
    const float* dec_bhh  = (const float*)d_in[14];
    const float* U_W      = (const float*)d_in[15];
    const float* U_b      = (const float*)d_in[16];
    const float* Wl_W     = (const float*)d_in[17];
    const float* Wl_b     = (const float*)d_in[18];
    const float* V_W      = (const float*)d_in[19];
    const float* V_b      = (const float*)d_in[20];
    const float* h2o_W    = (const float*)d_in[21];
    const float* h2o_b    = (const float*)d_in[22];
    float* outp = (float*)d_out;

    float *h0, *enc_out, *giE, *giD;
    float *Wenc, *Wdec, *WgiE, *WgiD, *bgE, *bgD, *UWTp, *WlTp, *Ubp, *Wlbp, *Vp;
    __nv_bfloat16 *Uobf, *encbf;
    cudaGetSymbolAddress((void**)&h0, g_h0);
    cudaGetSymbolAddress((void**)&enc_out, g_enc_out);
    cudaGetSymbolAddress((void**)&encbf, g_enc_bf);
    cudaGetSymbolAddress((void**)&Uobf, g_Uobf);
    cudaGetSymbolAddress((void**)&giE, g_giE);
    cudaGetSymbolAddress((void**)&giD, g_giD);
    cudaGetSymbolAddress((void**)&Wenc, g_Wenc);
    cudaGetSymbolAddress((void**)&Wdec, g_Wdec);
    cudaGetSymbolAddress((void**)&WgiE, g_WgiE);
    cudaGetSymbolAddress((void**)&WgiD, g_WgiD);
    cudaGetSymbolAddress((void**)&bgE, g_bgE);
    cudaGetSymbolAddress((void**)&bgD, g_bgD);
    cudaGetSymbolAddress((void**)&UWTp, g_UWTp);
    cudaGetSymbolAddress((void**)&WlTp, g_WlTp);
    cudaGetSymbolAddress((void**)&Ubp, g_Ubp);
    cudaGetSymbolAddress((void**)&Wlbp, g_Wlbp);
    cudaGetSymbolAddress((void**)&Vp, g_Vp);

    const size_t sm_enc = (size_t)(128 * 16 + 2 * 16 * 384 + ROWS * 384) * 4;   // 78848
    const size_t sm_dec = (size_t)(256 * 16 + 2 * 16 * 384 + ROWS * 384
                                   + ROWS * 132 + TT * ROWS + ROWS) * 4;        // 97680
    const size_t sm_uo  = (size_t)(HH * HS + HH * 36) * 4;
    cudaFuncSetAttribute((const void*)gruE_all_kernel,
                         cudaFuncAttributeMaxDynamicSharedMemorySize, (int)sm_enc);
    cudaFuncSetAttribute((const void*)gruD_all_kernel,
                         cudaFuncAttributeMaxDynamicSharedMemorySize, (int)sm_dec);
    cudaFuncSetAttribute((const void*)uo_kernel,
                         cudaFuncAttributeMaxDynamicSharedMemorySize, (int)sm_uo);

    const int total_w = 128 * 384 + 256 * 384 + ENC_ * 384 + DEC_ * 384 + 384
                      + 2 * HH * HS + 3 * HS;
    prep_weights<<<(total_w + 255) / 256, 256>>>(enc_Wih, enc_Whh, dec_Wih, dec_Whh,
                                                 U_W, U_b, Wl_W, Wl_b, V_W,
                                                 enc_bih, enc_bhh, dec_bih, dec_bhh);

    s2h_kernel<<<BB, 128>>>(ann, s2h_W1, s2h_b1, s2h_W2, s2h_b2, h0);

    gi_kernel<ENC_><<<TT * BB / 16, 384>>>(enc_data, WgiE, bgE, giE);

    gruE_all_kernel<<<NBLK, 384, sm_enc>>>(h0, Wenc, giE, enc_bhh, enc_out, encbf);

    gi_kernel<DEC_><<<NSTEPS * BB / 16, 384>>>(dec_data, WgiD, bgD, giD);

    uo_kernel<<<TT * BB / 32, 256, sm_uo>>>(enc_out, UWTp, Ubp, Uobf);

    const float* enc_last = enc_out + (size_t)(TT - 1) * BB * HS;
    gruD_all_kernel<<<NBLK, 448, sm_dec>>>(
        enc_last, Wdec, giD, dec_bhh, Uobf, encbf,
        WlTp, Wlbp, Vp, V_b, enc_data, h2o_W, h2o_b, outp);
}